// round 12
// baseline (speedup 1.0000x reference)
#include <cuda_runtime.h>
#include <cuda_bf16.h>
#include <math.h>
#include <cstdint>

// ============================================================================
// BiDirectionalSymplecticLayer — fused persistent kernel, FP8 e4m3 edition.
// BM=128 rows/CTA, 512 threads. All 8 gradient evals local. GEMMs via
// mma.sync.m16n8k32.e4m3 (2x MAC/instr vs bf16). H kept in BOTH e4m3 (MMA
// operand) and bf16 (derivative factor). Weights pre-scaled x16, G tiles
// scaled x64 to avoid e4m3 denormals; scales folded into epilogue constants.
// K=256 = 2 chunks of k128/pass, fully prefetched cross-pass.
// ============================================================================

#define D       256
#define FD      128
#define MTOT    16384
#define BHALF   8192
#define DT_MAG  0.1f
#define BM      128
#define NTH     512

// smem layout (bytes)
#define OFF_Hb  0                        // H bf16 tile: 128 x 512B (derivative)
#define OFF_Hq  65536                    // H e4m3 tile: 128 x 256B (MMA A, pass2)
#define OFF_Gq  98304                    // G e4m3 tile: 128 x 256B (MMA A, pass3/4)
#define OFF_A0  98304                    // A staging overlays G (pass 1 only)
#define OFF_A1  (98304 + 16384)
#define OFF_B0  131072                   // 3 x 32KB B staging
#define BBUF_SZ 32768
#define SMEM_TOTAL 229376

__device__ float   g_S  [MTOT * D];      // fp32 master state [q|p]
__device__ uint8_t g_S8 [MTOT * D];      // e4m3 state shadow
__device__ uint8_t g_W1q [D * D];        // 16*W1   [n][k]
__device__ uint8_t g_W2q [D * D];        // 16*W2   [n][k]
__device__ uint8_t g_W1Tq[D * D];        // 16*W1^T [n][k]
__device__ uint8_t g_W2Tq[D * D];        // 16*W2^T [n][k]

// ------------------------------- helpers ------------------------------------
__device__ __forceinline__ void cpa16(uint32_t dst, const void* src) {
    asm volatile("cp.async.cg.shared.global [%0], [%1], 16;"
                 :: "r"(dst), "l"(src) : "memory");
}
__device__ __forceinline__ uint32_t smem_u32(const void* p) {
    uint32_t r;
    asm("{ .reg .u64 t; cvta.to.shared.u64 t, %1; cvt.u32.u64 %0, t; }"
        : "=r"(r) : "l"(p));
    return r;
}
__device__ __forceinline__ void mma32(float* c, const uint32_t* a, const uint32_t* b) {
    asm volatile(
        "mma.sync.aligned.m16n8k32.row.col.f32.e4m3.e4m3.f32 "
        "{%0,%1,%2,%3}, {%4,%5,%6,%7}, {%8,%9}, {%0,%1,%2,%3};"
        : "+f"(c[0]), "+f"(c[1]), "+f"(c[2]), "+f"(c[3])
        : "r"(a[0]), "r"(a[1]), "r"(a[2]), "r"(a[3]), "r"(b[0]), "r"(b[1]));
}
#define LDMX4(r, addr) \
    asm volatile("ldmatrix.sync.aligned.m8n8.x4.shared.b16 {%0,%1,%2,%3}, [%4];" \
                 : "=r"((r)[0]), "=r"((r)[1]), "=r"((r)[2]), "=r"((r)[3]) \
                 : "r"(addr))
__device__ __forceinline__ uint32_t pk2(float x, float y) {       // bf16x2
    __nv_bfloat162 h = __floats2bfloat162_rn(x, y);
    return *reinterpret_cast<uint32_t*>(&h);
}
__device__ __forceinline__ float2 up2(uint32_t u) {
    __nv_bfloat162 h = *reinterpret_cast<__nv_bfloat162*>(&u);
    return make_float2(__bfloat162float(h.x), __bfloat162float(h.y));
}
__device__ __forceinline__ uint16_t pk_e4(float x, float y) {     // e4m3x2 {lo=x}
    uint16_t v;
    asm("cvt.rn.satfinite.e4m3x2.f32 %0, %1, %2;" : "=h"(v) : "f"(y), "f"(x));
    return v;
}
__device__ __forceinline__ uint8_t f2e4(float x) {
    uint16_t v;
    asm("cvt.rn.satfinite.e4m3x2.f32 %0, %1, %2;" : "=h"(v) : "f"(0.0f), "f"(x));
    return (uint8_t)v;
}
// tanh = 1 - 2/(1+e^{2x}); rcp via bit-trick + 2 Newton steps (FMA pipe)
__device__ __forceinline__ float ftanh(float x) {
    x = fminf(20.0f, fmaxf(-20.0f, x));
    float e;
    asm("ex2.approx.f32 %0, %1;" : "=f"(e) : "f"(x * 2.885390082f));
    float d = e + 1.0f;
    float y = __int_as_float(0x7EF311C3 - __float_as_int(d));
    y = y * (2.0f - d * y);
    y = y * (2.0f - d * y);
    return 1.0f - 2.0f * y;
}
// e4m3 tile byte address (256B rows, 16B-chunk swizzle)
__device__ __forceinline__ uint32_t q8a(int row, int nc) {
    return (uint32_t)(row * 256 + ((((nc >> 4) ^ (row & 7)) << 4) | (nc & 15)));
}

// stage one k128 B chunk (rows x 128B from 256B-row source); own group.
__device__ __forceinline__ void stageB(uint32_t dst, const uint8_t* W, int ck,
                                       int rows, int tid) {
    const uint8_t* src = W + ck * 128;
    const int n = rows >> 6;                  // rows*8 xfers / 512 threads
    for (int i = 0; i < n; i++) {
        int idx = tid + (i << 9);
        int row = idx >> 3, c = idx & 7;
        cpa16(dst + row * 128 + ((c ^ (row & 7)) << 4),
              src + (size_t)row * 256 + c * 16);
    }
    asm volatile("cp.async.commit_group;" ::: "memory");
}

// --------------------------- prologue kernel --------------------------------
__global__ void prep_kernel(const float* __restrict__ W1,
                            const float* __restrict__ W2) {
    int idx = blockIdx.x * blockDim.x + threadIdx.x;
    int r = idx >> 8, c = idx & 255;
    uint8_t v1 = f2e4(16.0f * W1[idx]);
    uint8_t v2 = f2e4(16.0f * W2[idx]);
    g_W1q[idx] = v1;
    g_W2q[idx] = v2;
    g_W1Tq[c * D + r] = v1;
    g_W2Tq[c * D + r] = v2;
}

// ------------------------------ fused pass ----------------------------------
//  MODE 0: A = staged g_S8,  B = 16*W1^T -> Hb/Hq = tanh(acc/16 + b1)
//  MODE 1: A = Hq tile,      B = 16*W2^T -> Gq = 64*wout*(1-tanh(acc/16+b2)^2)
//  MODE 2: A = Gq tile,      B = 16*W2   -> Gq = (acc/16)*(1-Hb^2)  (in place)
//  MODE 3: A = Gq tile,      B = 16*W1   -> full kick (acc = 1024*dH)
//  MODE 4: A = Gq tile,      B = 16*W1   -> half kick (NT=4)
template <int MODE, int NT>
__device__ __forceinline__ void pass_gemm(char* smem, uint32_t sbase,
                                          int m0, float dtv,
                                          uint32_t bufB0, uint32_t bufB1,
                                          const uint8_t* nextB, int nextRows,
                                          uint32_t nxt0, uint32_t nxt1,
                                          const float* __restrict__ b1g,
                                          const float* __restrict__ b2g,
                                          const float* __restrict__ wog) {
    const int tid  = threadIdx.x;
    const int wid  = tid >> 5;
    const int lane = tid & 31;
    const int g    = lane >> 2;
    const int t    = lane & 3;
    const int wm   = (wid & 3) * 32;
    const int wn   = (wid >> 2) * (NT * 8);

    uint32_t* Htw = (uint32_t*)(smem + OFF_Hb);
    const uint32_t* Ht = (const uint32_t*)(smem + OFF_Hb);

    // A staging for MODE 0: k128 chunk = 128 rows x 128B, own group
    auto stageA = [&](int ck, uint32_t dstOff) {
        const uint8_t* src = g_S8 + (size_t)m0 * D + ck * 128;
#pragma unroll
        for (int i = 0; i < 2; i++) {
            int idx = tid + (i << 9);
            int row = idx >> 3, c = idx & 7;
            cpa16(sbase + dstOff + row * 128 + ((c ^ (row & 7)) << 4),
                  src + (size_t)row * 256 + c * 16);
        }
        asm volatile("cp.async.commit_group;" ::: "memory");
    };

    if (MODE == 0) {
        __syncthreads();     // g_S8 writes -> cp.async; frees G region (overlay)
        stageA(0, OFF_A0);
        stageA(1, OFF_A1);
    }

    float acc[2][NT][4];
#pragma unroll
    for (int f = 0; f < 2; f++)
#pragma unroll
        for (int nf = 0; nf < NT; nf++)
#pragma unroll
            for (int r = 0; r < 4; r++) acc[f][nf][r] = 0.0f;

    // per-lane fragment address pieces
    const uint32_t aRowS = (uint32_t)(wm + (lane & 15)) * 128;   // staged A
    const int      ax7   = lane & 7;
    const int      akh   = lane >> 4;
    const uint32_t bRow  =
        (uint32_t)(wn + ((lane >> 4) << 3) + (lane & 7)) * 128;  // staged B
    const int      bkh   = (lane >> 3) & 1;
    uint32_t rrb[2];                                             // resident A
#pragma unroll
    for (int f = 0; f < 2; f++)
        rrb[f] = sbase + ((MODE == 1) ? OFF_Hq : OFF_Gq) +
                 (uint32_t)(wm + f * 16 + (lane & 15)) * 256;

#pragma unroll
    for (int kc = 0; kc < 2; kc++) {
        if (kc == 0) asm volatile("cp.async.wait_group 1;" ::: "memory");
        else         asm volatile("cp.async.wait_group 0;" ::: "memory");
        __syncthreads();

        const uint32_t aB = sbase + (kc ? OFF_A1 : OFF_A0) + aRowS;
        const uint32_t bB = (kc ? bufB1 : bufB0) + bRow;

#pragma unroll
        for (int kk = 0; kk < 4; kk++) {
            const int kg = kc * 4 + kk;
            uint32_t a[2][4], bb[NT][2];
            if (MODE == 0) {
                const uint32_t sa = (uint32_t)((((kk << 1) + akh) ^ ax7) << 4);
#pragma unroll
                for (int f = 0; f < 2; f++) LDMX4(a[f], aB + f * 2048 + sa);
            } else {
                const uint32_t sa = (uint32_t)((((kg << 1) + akh) ^ ax7) << 4);
#pragma unroll
                for (int f = 0; f < 2; f++) LDMX4(a[f], rrb[f] + sa);
            }
            const uint32_t sb = (uint32_t)((((kk << 1) + bkh) ^ ax7) << 4);
#pragma unroll
            for (int j = 0; j < NT / 2; j++) {
                uint32_t r_[4];
                LDMX4(r_, bB + j * 2048 + sb);
                bb[2*j][0]   = r_[0];  bb[2*j][1]   = r_[1];
                bb[2*j+1][0] = r_[2];  bb[2*j+1][1] = r_[3];
            }
#pragma unroll
            for (int f = 0; f < 2; f++)
#pragma unroll
                for (int nf = 0; nf < NT; nf++)
                    mma32(acc[f][nf], a[f], bb[nf]);
        }
    }

    // cross-pass prefetch of next pass's 2 B chunks (weights only).
    // nxt0 is an untouched buffer; nxt1 == bufB0, fully consumed before kc=1's
    // entry barrier which every warp has passed.
    if (nextB) {
        stageB(nxt0, nextB, 0, nextRows, tid);
        stageB(nxt1, nextB, 1, nextRows, tid);
    }
    if (MODE == 2) __syncthreads();   // in-place Gq overwrite: all MMA reads done

    // ------------------------------ epilogue --------------------------------
#pragma unroll
    for (int f = 0; f < 2; f++) {
        const int r = wm + f * 16 + g;
#pragma unroll
        for (int nf = 0; nf < NT; nf++) {
            const int nc = wn + nf * 8 + 2 * t;
            const int ws = (nc >> 1) ^ (g << 2);     // bf16 H tile word col
            float c0 = acc[f][nf][0], c1 = acc[f][nf][1];
            float c2 = acc[f][nf][2], c3 = acc[f][nf][3];

            if (MODE == 0) {
                float bv0 = __ldg(b1g + nc), bv1 = __ldg(b1g + nc + 1);
                float h0 = ftanh(c0 * 0.0625f + bv0), h1 = ftanh(c1 * 0.0625f + bv1);
                float h2 = ftanh(c2 * 0.0625f + bv0), h3 = ftanh(c3 * 0.0625f + bv1);
                Htw[r * 128 + ws]       = pk2(h0, h1);
                Htw[(r + 8) * 128 + ws] = pk2(h2, h3);
                *(uint16_t*)(smem + OFF_Hq + q8a(r, nc))     = pk_e4(h0, h1);
                *(uint16_t*)(smem + OFF_Hq + q8a(r + 8, nc)) = pk_e4(h2, h3);
            } else if (MODE == 1) {
                float bv0 = __ldg(b2g + nc), bv1 = __ldg(b2g + nc + 1);
                float wv0 = __ldg(wog + nc) * 64.0f, wv1 = __ldg(wog + nc + 1) * 64.0f;
                float t0 = ftanh(c0 * 0.0625f + bv0), t1 = ftanh(c1 * 0.0625f + bv1);
                float t2 = ftanh(c2 * 0.0625f + bv0), t3 = ftanh(c3 * 0.0625f + bv1);
                *(uint16_t*)(smem + OFF_Gq + q8a(r, nc)) =
                    pk_e4(wv0 * (1.0f - t0 * t0), wv1 * (1.0f - t1 * t1));
                *(uint16_t*)(smem + OFF_Gq + q8a(r + 8, nc)) =
                    pk_e4(wv0 * (1.0f - t2 * t2), wv1 * (1.0f - t3 * t3));
            } else if (MODE == 2) {
                float2 h0 = up2(Ht[r * 128 + ws]);
                float2 h1 = up2(Ht[(r + 8) * 128 + ws]);
                *(uint16_t*)(smem + OFF_Gq + q8a(r, nc)) =
                    pk_e4(c0 * 0.0625f * (1.0f - h0.x * h0.x),
                          c1 * 0.0625f * (1.0f - h0.y * h0.y));
                *(uint16_t*)(smem + OFF_Gq + q8a(r + 8, nc)) =
                    pk_e4(c2 * 0.0625f * (1.0f - h1.x * h1.x),
                          c3 * 0.0625f * (1.0f - h1.y * h1.y));
            } else {
                const float cp_ = dtv * (0.5f / 1024.0f);
                const float cq_ = dtv * (1.0f / 1024.0f);
                const int grow = m0 + r;
                if (NT == 4 || nc < FD) {        // p -= 0.5*dt*dH[:, :FD]
                    float2* S0 = (float2*)(g_S + (size_t)grow * D + FD + nc);
                    float2* S1 = (float2*)(g_S + (size_t)(grow + 8) * D + FD + nc);
                    float2 p0 = *S0, p1 = *S1;
                    p0.x -= cp_ * c0;  p0.y -= cp_ * c1;
                    p1.x -= cp_ * c2;  p1.y -= cp_ * c3;
                    *S0 = p0;  *S1 = p1;
                    *(uint16_t*)(g_S8 + (size_t)grow * D + FD + nc)       = pk_e4(p0.x, p0.y);
                    *(uint16_t*)(g_S8 + (size_t)(grow + 8) * D + FD + nc) = pk_e4(p1.x, p1.y);
                } else {                          // q += dt*dH[:, FD:]
                    const int qc = nc - FD;
                    float2* S0 = (float2*)(g_S + (size_t)grow * D + qc);
                    float2* S1 = (float2*)(g_S + (size_t)(grow + 8) * D + qc);
                    float2 q0 = *S0, q1 = *S1;
                    q0.x += cq_ * c0;  q0.y += cq_ * c1;
                    q1.x += cq_ * c2;  q1.y += cq_ * c3;
                    *S0 = q0;  *S1 = q1;
                    *(uint16_t*)(g_S8 + (size_t)grow * D + qc)       = pk_e4(q0.x, q0.y);
                    *(uint16_t*)(g_S8 + (size_t)(grow + 8) * D + qc) = pk_e4(q1.x, q1.y);
                }
            }
        }
    }
    // no trailing barrier: every pass begins with wait+__syncthreads before
    // reading staged buffers or tiles; MODE 0/2 carry their extra barriers.
}

// ------------------------------ fused kernel --------------------------------
__global__ void __launch_bounds__(NTH, 1)
fused_kernel(const float* __restrict__ b1, const float* __restrict__ b2,
             const float* __restrict__ wo, const float* __restrict__ x,
             float* __restrict__ out) {
    extern __shared__ __align__(1024) char smem[];
    const uint32_t sbase = smem_u32(smem);
    const int tid = threadIdx.x;
    const int m0  = blockIdx.x * BM;
    const int bwd = (m0 >= BHALF);
    const int b0  = m0 & (BHALF - 1);

    // prefetch first pass's 2 B chunks (bufs 0,1) — overlaps init
    stageB(sbase + OFF_B0,           g_W1Tq, 0, 256, tid);
    stageB(sbase + OFF_B0 + BBUF_SZ, g_W1Tq, 1, 256, tid);

    // init this CTA's 128 state rows from x (row-private)
    for (int i = tid; i < BM * 128; i += NTH) {
        int r = i >> 7, f = i & 127;
        size_t xb = (size_t)(b0 + r) * 8192;
        float xm  = x[xb + 4096 + f];
        float xm1 = x[xb + 3968 + f];
        float q = xm, p = xm - xm1;
        size_t srow = (size_t)(m0 + r) * D;
        g_S[srow + f]      = q;
        g_S[srow + FD + f] = p;
        g_S8[srow + f]      = f2e4(q);
        g_S8[srow + FD + f] = f2e4(p);
    }

    const float dtv = bwd ? -DT_MAG : DT_MAG;
    int bs = 0;                 // buffer-start index; advances +2 mod 3 / pass
    auto BUF = [&](int i) {
        return sbase + OFF_B0 + (uint32_t)((bs + i) % 3) * BBUF_SZ;
    };

#pragma unroll 1
    for (int it = 0; it < 8; it++) {
        pass_gemm<0, 8>(smem, sbase, m0, dtv, BUF(0), BUF(1),
                        g_W2Tq, 256, BUF(2), BUF(0), b1, b2, wo);
        bs = (bs + 2) % 3;
        pass_gemm<1, 8>(smem, sbase, m0, dtv, BUF(0), BUF(1),
                        g_W2q, 256, BUF(2), BUF(0), b1, b2, wo);
        bs = (bs + 2) % 3;
        if ((it & 1) == 0) {
            pass_gemm<2, 8>(smem, sbase, m0, dtv, BUF(0), BUF(1),
                            g_W1q, 256, BUF(2), BUF(0), b1, b2, wo);
            bs = (bs + 2) % 3;
            pass_gemm<3, 8>(smem, sbase, m0, dtv, BUF(0), BUF(1),
                            g_W1Tq, 256, BUF(2), BUF(0), b1, b2, wo);
            bs = (bs + 2) % 3;
        } else {
            pass_gemm<2, 8>(smem, sbase, m0, dtv, BUF(0), BUF(1),
                            g_W1q, 128, BUF(2), BUF(0), b1, b2, wo);
            bs = (bs + 2) % 3;
            if (it < 7)
                pass_gemm<4, 4>(smem, sbase, m0, dtv, BUF(0), BUF(1),
                                g_W1Tq, 256, BUF(2), BUF(0), b1, b2, wo);
            else
                pass_gemm<4, 4>(smem, sbase, m0, dtv, BUF(0), BUF(1),
                                nullptr, 0, 0, 0, b1, b2, wo);
            bs = (bs + 2) % 3;
        }
    }

    // output: this CTA's rows -> disjoint column ranges of out
    __syncthreads();   // kick-epilogue g_S writes visible to all threads
    for (int i = tid; i < BM * 64; i += NTH) {
        int r = i >> 6, c4 = i & 63;
        float4 v = *(const float4*)(g_S + (size_t)(m0 + r) * D + c4 * 4);
        float* orow = out + (size_t)(b0 + r) * 768;
        if (bwd) *(float4*)(orow + c4 * 4) = v;          // [q_b | p_b]
        else     *(float4*)(orow + 512 + c4 * 4) = v;    // [q_f | p_f]
    }
    if (!bwd) {
        for (int i = tid; i < BM * 128; i += NTH) {
            int r = i >> 7, f = i & 127;
            size_t xb = (size_t)(b0 + r) * 8192;
            float xm  = x[xb + 4096 + f];
            float xm1 = x[xb + 3968 + f];
            float* orow = out + (size_t)(b0 + r) * 768;
            orow[256 + f] = xm;          // q_mid
            orow[384 + f] = xm - xm1;    // p_mid
        }
    }
}

// ---------------------------------------------------------------------------
extern "C" void kernel_launch(void* const* d_in, const int* in_sizes, int n_in,
                              void* d_out, int out_size) {
    const float* x    = (const float*)d_in[0];
    const float* W1   = (const float*)d_in[1];
    const float* b1   = (const float*)d_in[2];
    const float* W2   = (const float*)d_in[3];
    const float* b2   = (const float*)d_in[4];
    const float* Wout = (const float*)d_in[5];
    float* out = (float*)d_out;

    cudaFuncSetAttribute(fused_kernel,
                         cudaFuncAttributeMaxDynamicSharedMemorySize, SMEM_TOTAL);

    prep_kernel<<<D * D / 256, 256>>>(W1, W2);
    fused_kernel<<<MTOT / BM, NTH, SMEM_TOTAL>>>(b1, b2, Wout, x, out);
}

// round 13
// speedup vs baseline: 1.3048x; 1.3048x over previous
#include <cuda_runtime.h>
#include <cuda_bf16.h>
#include <math.h>
#include <cstdint>

// ============================================================================
// BiDirectionalSymplecticLayer — fused persistent kernel, 148-SM edition.
// M retiled: 144 CTAs x 112 rows + 4 CTAs x 64 rows (grid 148) so every SM
// carries MMA work; per-SMSP HMMA floor drops 1024->896 per pass. Warp map:
// 8 n-splits x 2 m-groups (warps 0-7: F=4 fragments, 8-15: F=3). bf16
// m16n8k16 datapath, swizzled resident H/G tiles, 3-buffer k64 cp.async
// pipeline with cross-pass weight prefetch (all from R10).
// ============================================================================

#define D       256
#define FD      128
#define MTOT    16384
#define BHALF   8192
#define DT_MAG  0.1f
#define NTH     512

// smem layout (bytes) — tiles sized for up to 128 rows
#define OFF_H   0                        // H tile: rows x 512B, swizzled
#define OFF_G   65536                    // G tile; A bufs overlay in MODE 0
#define OFF_A0  65536                    // A staging: 3 x (128 x 128B)
#define OFF_B0  131072                   // B staging: 3 x (256 x 128B)
#define ABUF_SZ 16384
#define BBUF_SZ 32768
#define SMEM_TOTAL (131072 + 3 * BBUF_SZ)   // 229376

__device__ float         g_S [MTOT * D];
__device__ __nv_bfloat16 g_Sb[MTOT * D];
__device__ __nv_bfloat16 g_W1b [D * D];    // W1  [n][k]
__device__ __nv_bfloat16 g_W2b [D * D];    // W2  [n][k]
__device__ __nv_bfloat16 g_W1Tb[D * D];    // W1^T [n][k]
__device__ __nv_bfloat16 g_W2Tb[D * D];    // W2^T [n][k]

// ------------------------------- helpers ------------------------------------
__device__ __forceinline__ void cpa16(uint32_t dst, const void* src) {
    asm volatile("cp.async.cg.shared.global [%0], [%1], 16;"
                 :: "r"(dst), "l"(src) : "memory");
}
__device__ __forceinline__ uint32_t smem_u32(const void* p) {
    uint32_t r;
    asm("{ .reg .u64 t; cvta.to.shared.u64 t, %1; cvt.u32.u64 %0, t; }"
        : "=r"(r) : "l"(p));
    return r;
}
__device__ __forceinline__ void mma16(float* c, const uint32_t* a, const uint32_t* b) {
    asm volatile(
        "mma.sync.aligned.m16n8k16.row.col.f32.bf16.bf16.f32 "
        "{%0,%1,%2,%3}, {%4,%5,%6,%7}, {%8,%9}, {%0,%1,%2,%3};"
        : "+f"(c[0]), "+f"(c[1]), "+f"(c[2]), "+f"(c[3])
        : "r"(a[0]), "r"(a[1]), "r"(a[2]), "r"(a[3]), "r"(b[0]), "r"(b[1]));
}
#define LDMX4(r, addr) \
    asm volatile("ldmatrix.sync.aligned.m8n8.x4.shared.b16 {%0,%1,%2,%3}, [%4];" \
                 : "=r"((r)[0]), "=r"((r)[1]), "=r"((r)[2]), "=r"((r)[3]) \
                 : "r"(addr))
__device__ __forceinline__ uint32_t pk2(float x, float y) {
    __nv_bfloat162 h = __floats2bfloat162_rn(x, y);
    return *reinterpret_cast<uint32_t*>(&h);
}
__device__ __forceinline__ float2 up2(uint32_t u) {
    __nv_bfloat162 h = *reinterpret_cast<__nv_bfloat162*>(&u);
    return make_float2(__bfloat162float(h.x), __bfloat162float(h.y));
}
__device__ __forceinline__ float ftanh(float x) {
    x = fminf(20.0f, fmaxf(-20.0f, x));
    float e;
    asm("ex2.approx.f32 %0, %1;" : "=f"(e) : "f"(x * 2.885390082f));
    float d = e + 1.0f;
    float y = __int_as_float(0x7EF311C3 - __float_as_int(d));
    y = y * (2.0f - d * y);
    y = y * (2.0f - d * y);
    return 1.0f - 2.0f * y;
}

// stage one k64 B chunk (rows x 128B) into a swizzled buffer; own group.
__device__ __forceinline__ void stageB_rows(uint32_t dst, const __nv_bfloat16* Bg0,
                                            int kc, int rows, int tid) {
    const __nv_bfloat16* Bg = Bg0 + kc * 64;
    const int n = rows >> 6;
    for (int i = 0; i < n; i++) {
        int idx = tid + (i << 9);
        int row = idx >> 3, c = idx & 7;
        cpa16(dst + row * 128 + ((c ^ (row & 7)) << 4),
              Bg + (size_t)row * D + c * 8);
    }
    asm volatile("cp.async.commit_group;" ::: "memory");
}

// --------------------------- prologue kernel --------------------------------
__global__ void prep_kernel(const float* __restrict__ W1,
                            const float* __restrict__ W2) {
    int idx = blockIdx.x * blockDim.x + threadIdx.x;
    int r = idx >> 8, c = idx & 255;
    __nv_bfloat16 v1 = __float2bfloat16(W1[idx]);
    __nv_bfloat16 v2 = __float2bfloat16(W2[idx]);
    g_W1b[idx] = v1;
    g_W2b[idx] = v2;
    g_W1Tb[c * D + r] = v1;
    g_W2Tb[c * D + r] = v2;
}

// ------------------------------ fused pass ----------------------------------
//  MODE 0: A = staged g_Sb, B = g_W1Tb -> H = tanh(acc + b1)
//  MODE 1: A = H tile,      B = g_W2Tb -> G = wout*(1 - tanh(acc+b2)^2)
//  MODE 2: A = G tile,      B = g_W2b  -> G = acc*(1 - H^2)   (in place)
//  MODE 3: A = G tile,      B = g_W1b  -> full kick (NT=4, N=256)
//  MODE 4: A = G tile,      B = g_W1b  -> half kick (NT=2, N=128)
// Warp map: wn = (wid&7)*(NT*8); m-group via runtime (mbase, F), F<=4,
// warp-uniform (guarded ldmatrix/mma loops are sync-legal).
template <int MODE, int NT>
__device__ __forceinline__ void pass_gemm(char* smem, uint32_t sbase,
                                          int m0, int cbm, int mbase, int F,
                                          int bs,
                                          const __nv_bfloat16* nextB, int nextRows,
                                          const float* __restrict__ b1g,
                                          const float* __restrict__ b2g,
                                          const float* __restrict__ wog) {
    const int tid  = threadIdx.x;
    const int wid  = tid >> 5;
    const int lane = tid & 31;
    const int g    = lane >> 2;
    const int t    = lane & 3;
    const int wn   = (wid & 7) * (NT * 8);
    const int NROW = NT * 64;                 // B tile rows: 256 or 128

    const uint32_t* Ht  = (const uint32_t*)(smem + OFF_H);
    uint32_t*       Htw = (uint32_t*)(smem + OFF_H);
    uint32_t*       Gt  = (uint32_t*)(smem + OFF_G);

    const __nv_bfloat16* Bsrc =
        (MODE == 0) ? g_W1Tb : (MODE == 1) ? g_W2Tb :
        (MODE == 2) ? g_W2b : g_W1b;

    const uint32_t Bbase = sbase + OFF_B0;
    const uint32_t Abase = sbase + OFF_A0;
    auto rotB = [&](uint32_t v) { return (v == Bbase + 2 * BBUF_SZ) ? Bbase : v + BBUF_SZ; };
    auto rotA = [&](uint32_t v) { return (v == Abase + 2 * ABUF_SZ) ? Abase : v + ABUF_SZ; };

    uint32_t curB = Bbase + (uint32_t)bs * BBUF_SZ;
    uint32_t curA = Abase + (uint32_t)bs * ABUF_SZ;
    uint32_t stgB = rotB(rotB(curB));
    uint32_t stgA = rotA(rotA(curA));

    auto stage = [&](int kc, uint32_t bdst, uint32_t adst) {
        const __nv_bfloat16* Bg = Bsrc + kc * 64;
#pragma unroll
        for (int i = 0; i < NROW / 64; i++) {
            int idx = tid + (i << 9);
            int row = idx >> 3, c = idx & 7;
            cpa16(bdst + row * 128 + ((c ^ (row & 7)) << 4),
                  Bg + (size_t)row * D + c * 8);
        }
        if (MODE == 0) {
            const __nv_bfloat16* Ag = g_Sb + (size_t)m0 * D + kc * 64;
#pragma unroll
            for (int i = 0; i < 2; i++) {
                int idx = tid + (i << 9);
                int row = idx >> 3, c = idx & 7;
                if (row < cbm)
                    cpa16(adst + row * 128 + ((c ^ (row & 7)) << 4),
                          Ag + (size_t)row * D + c * 8);
            }
        }
        asm volatile("cp.async.commit_group;" ::: "memory");
    };
    auto stageA1 = [&](int kc, uint32_t adst) {
        const __nv_bfloat16* Ag = g_Sb + (size_t)m0 * D + kc * 64;
#pragma unroll
        for (int i = 0; i < 2; i++) {
            int idx = tid + (i << 9);
            int row = idx >> 3, c = idx & 7;
            if (row < cbm)
                cpa16(adst + row * 128 + ((c ^ (row & 7)) << 4),
                      Ag + (size_t)row * D + c * 8);
        }
        asm volatile("cp.async.commit_group;" ::: "memory");
    };

    if (MODE == 0) {
        __syncthreads();                 // g_Sb writes -> cp.async; frees G
        stageA1(0, curA);
        stageA1(1, rotA(curA));
    }

    float acc[4][NT][4];
#pragma unroll
    for (int f = 0; f < 4; f++)
#pragma unroll
        for (int nf = 0; nf < NT; nf++)
#pragma unroll
            for (int r = 0; r < 4; r++) acc[f][nf][r] = 0.0f;

    // per-lane fragment address pieces
    const uint32_t aRowS = (uint32_t)(mbase + (lane & 15)) * 128;  // staged A
    const int      x7    = lane & 7;
    const int      akh   = lane >> 4;
    const uint32_t bRow  =
        (uint32_t)(wn + ((lane >> 4) << 3) + (lane & 7)) * 128;
    const int      bkh   = (lane >> 3) & 1;
    const int hi4w = (lane >> 4) << 2;
    const int row7 = x7 << 2;
    uint32_t rrb[4];
#pragma unroll
    for (int f = 0; f < 4; f++)
        rrb[f] = sbase + ((MODE == 1) ? OFF_H : OFF_G) +
                 (uint32_t)(mbase + f * 16 + (lane & 15)) * 512;

#pragma unroll 1
    for (int kc = 0; kc < 4; kc++) {
        if (kc < 3) asm volatile("cp.async.wait_group 1;" ::: "memory");
        else        asm volatile("cp.async.wait_group 0;" ::: "memory");
        __syncthreads();
        if (kc < 2) stage(kc + 2, stgB, stgA);

        const uint32_t aB = curA + aRowS;
        const uint32_t bB = curB + bRow;

#pragma unroll
        for (int kk = 0; kk < 4; kk++) {
            const int kg = kc * 4 + kk;
            uint32_t a[4][4], bb[NT][2];
            if (MODE == 0) {
                const uint32_t sa = (uint32_t)((((kk << 1) + akh) ^ x7) << 4);
#pragma unroll
                for (int f = 0; f < 4; f++)
                    if (f < F) LDMX4(a[f], aB + f * 2048 + sa);
            } else {
                const uint32_t s4 = (uint32_t)((((kg << 3) + hi4w) ^ row7) << 2);
#pragma unroll
                for (int f = 0; f < 4; f++)
                    if (f < F) LDMX4(a[f], rrb[f] + s4);
            }
            const uint32_t sb4 = (uint32_t)((((kk << 1) + bkh) ^ x7) << 4);
#pragma unroll
            for (int j = 0; j < NT / 2; j++) {
                uint32_t r_[4];
                LDMX4(r_, bB + j * 2048 + sb4);
                bb[2*j][0]   = r_[0];  bb[2*j][1]   = r_[1];
                bb[2*j+1][0] = r_[2];  bb[2*j+1][1] = r_[3];
            }
#pragma unroll
            for (int f = 0; f < 4; f++)
                if (f < F)
#pragma unroll
                    for (int nf = 0; nf < NT; nf++)
                        mma16(acc[f][nf], a[f], bb[nf]);
        }
        curB = rotB(curB);  curA = rotA(curA);
        stgB = rotB(stgB);  stgA = rotA(stgA);
    }

    // cross-pass prefetch (bufs bs+1, bs+2 of next pass) — clobber-free
    if (nextB) {
        stageB_rows(curB, nextB, 0, nextRows, tid);
        stageB_rows(rotB(curB), nextB, 1, nextRows, tid);
    }
    if (MODE == 2) __syncthreads();   // in-place G overwrite: all reads done

    // ------------------------------ epilogue --------------------------------
#pragma unroll
    for (int f = 0; f < 4; f++) {
        if (f >= F) continue;
        const int r = mbase + f * 16 + g;        // local row; r&7 == g
#pragma unroll
        for (int nf = 0; nf < NT; nf++) {
            const int nc = wn + nf * 8 + 2 * t;
            const int ws = (nc >> 1) ^ (g << 2);
            float c0 = acc[f][nf][0], c1 = acc[f][nf][1];
            float c2 = acc[f][nf][2], c3 = acc[f][nf][3];

            if (MODE == 0) {
                float bv0 = __ldg(b1g + nc), bv1 = __ldg(b1g + nc + 1);
                Htw[r * 128 + ws]       = pk2(ftanh(c0 + bv0), ftanh(c1 + bv1));
                Htw[(r + 8) * 128 + ws] = pk2(ftanh(c2 + bv0), ftanh(c3 + bv1));
            } else if (MODE == 1) {
                float bv0 = __ldg(b2g + nc), bv1 = __ldg(b2g + nc + 1);
                float wv0 = __ldg(wog + nc), wv1 = __ldg(wog + nc + 1);
                float t0 = ftanh(c0 + bv0), t1 = ftanh(c1 + bv1);
                float t2 = ftanh(c2 + bv0), t3 = ftanh(c3 + bv1);
                Gt[r * 128 + ws]       = pk2(wv0 * (1.0f - t0 * t0),
                                             wv1 * (1.0f - t1 * t1));
                Gt[(r + 8) * 128 + ws] = pk2(wv0 * (1.0f - t2 * t2),
                                             wv1 * (1.0f - t3 * t3));
            } else if (MODE == 2) {
                float2 h0 = up2(Ht[r * 128 + ws]);
                float2 h1 = up2(Ht[(r + 8) * 128 + ws]);
                Gt[r * 128 + ws]       = pk2(c0 * (1.0f - h0.x * h0.x),
                                             c1 * (1.0f - h0.y * h0.y));
                Gt[(r + 8) * 128 + ws] = pk2(c2 * (1.0f - h1.x * h1.x),
                                             c3 * (1.0f - h1.y * h1.y));
            } else {
                const int grow = m0 + r;
                const float dA = (grow < BHALF) ? DT_MAG : -DT_MAG;
                const float dB = (grow + 8 < BHALF) ? DT_MAG : -DT_MAG;
                if (NT == 2 || nc < FD) {        // p -= 0.5*dt*dH[:, :FD]
                    float2* S0 = (float2*)(g_S + (size_t)grow * D + FD + nc);
                    float2* S1 = (float2*)(g_S + (size_t)(grow + 8) * D + FD + nc);
                    float2 p0 = *S0, p1 = *S1;
                    p0.x -= 0.5f * dA * c0;  p0.y -= 0.5f * dA * c1;
                    p1.x -= 0.5f * dB * c2;  p1.y -= 0.5f * dB * c3;
                    *S0 = p0;  *S1 = p1;
                    *(uint32_t*)(g_Sb + (size_t)grow * D + FD + nc)       = pk2(p0.x, p0.y);
                    *(uint32_t*)(g_Sb + (size_t)(grow + 8) * D + FD + nc) = pk2(p1.x, p1.y);
                } else {                          // q += dt*dH[:, FD:]
                    const int qc = nc - FD;
                    float2* S0 = (float2*)(g_S + (size_t)grow * D + qc);
                    float2* S1 = (float2*)(g_S + (size_t)(grow + 8) * D + qc);
                    float2 q0 = *S0, q1 = *S1;
                    q0.x += dA * c0;  q0.y += dA * c1;
                    q1.x += dB * c2;  q1.y += dB * c3;
                    *S0 = q0;  *S1 = q1;
                    *(uint32_t*)(g_Sb + (size_t)grow * D + qc)       = pk2(q0.x, q0.y);
                    *(uint32_t*)(g_Sb + (size_t)(grow + 8) * D + qc) = pk2(q1.x, q1.y);
                }
            }
        }
    }
}

// ------------------------------ fused kernel --------------------------------
__global__ void __launch_bounds__(NTH, 1)
fused_kernel(const float* __restrict__ b1, const float* __restrict__ b2,
             const float* __restrict__ wo, const float* __restrict__ x,
             float* __restrict__ out) {
    extern __shared__ __align__(1024) char smem[];
    const uint32_t sbase = smem_u32(smem);
    const int tid = threadIdx.x;
    const int wid = tid >> 5;
    const int cta = blockIdx.x;

    int m0, cbm;
    if (cta < 144) { m0 = cta * 112;                 cbm = 112; }
    else           { m0 = 16128 + (cta - 144) * 64;  cbm = 64; }
    int mbase, F;
    if (cbm == 112) { mbase = (wid < 8) ? 0 : 64;  F = (wid < 8) ? 4 : 3; }
    else            { mbase = (wid < 8) ? 0 : 32;  F = 2; }

    // prefetch first pass's B chunks (bufs 0,1) — overlaps init below
    stageB_rows(sbase + OFF_B0, g_W1Tb, 0, 256, tid);
    stageB_rows(sbase + OFF_B0 + BBUF_SZ, g_W1Tb, 1, 256, tid);

    // init this CTA's state rows from x (row-private)
    for (int i = tid; i < cbm * 128; i += NTH) {
        int r = i >> 7, f = i & 127;
        int grow = m0 + r;
        int xi = (grow < BHALF) ? grow : grow - BHALF;
        size_t xb = (size_t)xi * 8192;
        float xm  = x[xb + 4096 + f];
        float xm1 = x[xb + 3968 + f];
        float q = xm, p = xm - xm1;
        size_t srow = (size_t)grow * D;
        g_S[srow + f]      = q;
        g_S[srow + FD + f] = p;
        g_Sb[srow + f]      = __float2bfloat16(q);
        g_Sb[srow + FD + f] = __float2bfloat16(p);
    }

    int bs = 0;
    auto inc = [&]() { bs = (bs == 2) ? 0 : bs + 1; };

#pragma unroll 1
    for (int it = 0; it < 8; it++) {
        pass_gemm<0, 4>(smem, sbase, m0, cbm, mbase, F, bs, g_W2Tb, 256, b1, b2, wo); inc();
        pass_gemm<1, 4>(smem, sbase, m0, cbm, mbase, F, bs, g_W2b, 256, b1, b2, wo);  inc();
        if ((it & 1) == 0) {
            pass_gemm<2, 4>(smem, sbase, m0, cbm, mbase, F, bs, g_W1b, 256, b1, b2, wo); inc();
            pass_gemm<3, 4>(smem, sbase, m0, cbm, mbase, F, bs, g_W1Tb, 256, b1, b2, wo); inc();
        } else {
            pass_gemm<2, 4>(smem, sbase, m0, cbm, mbase, F, bs, g_W1b, 128, b1, b2, wo); inc();
            if (it < 7) { pass_gemm<4, 2>(smem, sbase, m0, cbm, mbase, F, bs, g_W1Tb, 256, b1, b2, wo); }
            else        { pass_gemm<4, 2>(smem, sbase, m0, cbm, mbase, F, bs, nullptr, 0, b1, b2, wo); }
            inc();
        }
    }

    // output: this CTA's rows -> disjoint column ranges of out
    __syncthreads();   // kick-epilogue g_S writes visible to all threads
    for (int i = tid; i < cbm * 64; i += NTH) {
        int r = i >> 6, c4 = i & 63;
        int grow = m0 + r;
        float4 v = *(const float4*)(g_S + (size_t)grow * D + c4 * 4);
        int bwd = grow >= BHALF;
        float* orow = out + (size_t)(bwd ? grow - BHALF : grow) * 768;
        if (bwd) *(float4*)(orow + c4 * 4) = v;          // [q_b | p_b]
        else     *(float4*)(orow + 512 + c4 * 4) = v;    // [q_f | p_f]
    }
    for (int i = tid; i < cbm * 128; i += NTH) {
        int r = i >> 7, f = i & 127;
        int grow = m0 + r;
        if (grow < BHALF) {                              // fwd rows write mid
            size_t xb = (size_t)grow * 8192;
            float xm  = x[xb + 4096 + f];
            float xm1 = x[xb + 3968 + f];
            float* orow = out + (size_t)grow * 768;
            orow[256 + f] = xm;          // q_mid
            orow[384 + f] = xm - xm1;    // p_mid
        }
    }
}

// ---------------------------------------------------------------------------
extern "C" void kernel_launch(void* const* d_in, const int* in_sizes, int n_in,
                              void* d_out, int out_size) {
    const float* x    = (const float*)d_in[0];
    const float* W1   = (const float*)d_in[1];
    const float* b1   = (const float*)d_in[2];
    const float* W2   = (const float*)d_in[3];
    const float* b2   = (const float*)d_in[4];
    const float* Wout = (const float*)d_in[5];
    float* out = (float*)d_out;

    cudaFuncSetAttribute(fused_kernel,
                         cudaFuncAttributeMaxDynamicSharedMemorySize, SMEM_TOTAL);

    prep_kernel<<<D * D / 256, 256>>>(W1, W2);
    fused_kernel<<<148, NTH, SMEM_TOTAL>>>(b1, b2, Wout, x, out);
}

// round 14
// speedup vs baseline: 1.4656x; 1.1232x over previous
#include <cuda_runtime.h>
#include <cuda_bf16.h>
#include <math.h>
#include <cstdint>

// ============================================================================
// BiDirectionalSymplecticLayer — fused persistent kernel, 147-SM uniform-warp
// edition. 146 CTAs x 112 rows + 1 CTA x 32 rows. Warp map: 16 n-splits, each
// warp owns ALL CTA rows x 16 cols -> F=7 x NT=2 = 14 MMA/k-step per warp,
// UNIFORM (critical path cut 16->14 vs BM=128). F is compile-time (template).
// bf16 m16n8k16; swizzled resident H/G tiles; 3-buffer k64 cp.async pipeline;
// cross-pass weight prefetch.
// ============================================================================

#define D       256
#define FD      128
#define MTOT    16384
#define BHALF   8192
#define DT_MAG  0.1f
#define NTH     512

// smem layout (bytes) — tiles sized for up to 112 rows
#define OFF_H   0                        // H tile: rows x 512B, swizzled
#define OFF_G   57344                    // G tile; A bufs overlay in MODE 0
#define OFF_A0  57344                    // A staging: 3 x (112 x 128B)
#define OFF_B0  114688                   // B staging: 3 x (256 x 128B)
#define ABUF_SZ 14336
#define BBUF_SZ 32768
#define SMEM_TOTAL (114688 + 3 * BBUF_SZ)   // 212992

__device__ float         g_S [MTOT * D];
__device__ __nv_bfloat16 g_Sb[MTOT * D];
__device__ __nv_bfloat16 g_W1b [D * D];    // W1  [n][k]
__device__ __nv_bfloat16 g_W2b [D * D];    // W2  [n][k]
__device__ __nv_bfloat16 g_W1Tb[D * D];    // W1^T [n][k]
__device__ __nv_bfloat16 g_W2Tb[D * D];    // W2^T [n][k]

// ------------------------------- helpers ------------------------------------
__device__ __forceinline__ void cpa16(uint32_t dst, const void* src) {
    asm volatile("cp.async.cg.shared.global [%0], [%1], 16;"
                 :: "r"(dst), "l"(src) : "memory");
}
__device__ __forceinline__ uint32_t smem_u32(const void* p) {
    uint32_t r;
    asm("{ .reg .u64 t; cvta.to.shared.u64 t, %1; cvt.u32.u64 %0, t; }"
        : "=r"(r) : "l"(p));
    return r;
}
__device__ __forceinline__ void mma16(float* c, const uint32_t* a, const uint32_t* b) {
    asm volatile(
        "mma.sync.aligned.m16n8k16.row.col.f32.bf16.bf16.f32 "
        "{%0,%1,%2,%3}, {%4,%5,%6,%7}, {%8,%9}, {%0,%1,%2,%3};"
        : "+f"(c[0]), "+f"(c[1]), "+f"(c[2]), "+f"(c[3])
        : "r"(a[0]), "r"(a[1]), "r"(a[2]), "r"(a[3]), "r"(b[0]), "r"(b[1]));
}
#define LDMX4(r, addr) \
    asm volatile("ldmatrix.sync.aligned.m8n8.x4.shared.b16 {%0,%1,%2,%3}, [%4];" \
                 : "=r"((r)[0]), "=r"((r)[1]), "=r"((r)[2]), "=r"((r)[3]) \
                 : "r"(addr))
#define LDMX2(r, addr) \
    asm volatile("ldmatrix.sync.aligned.m8n8.x2.shared.b16 {%0,%1}, [%2];" \
                 : "=r"((r)[0]), "=r"((r)[1]) \
                 : "r"(addr))
__device__ __forceinline__ uint32_t pk2(float x, float y) {
    __nv_bfloat162 h = __floats2bfloat162_rn(x, y);
    return *reinterpret_cast<uint32_t*>(&h);
}
__device__ __forceinline__ float2 up2(uint32_t u) {
    __nv_bfloat162 h = *reinterpret_cast<__nv_bfloat162*>(&u);
    return make_float2(__bfloat162float(h.x), __bfloat162float(h.y));
}
__device__ __forceinline__ float ftanh(float x) {
    x = fminf(20.0f, fmaxf(-20.0f, x));
    float e;
    asm("ex2.approx.f32 %0, %1;" : "=f"(e) : "f"(x * 2.885390082f));
    float d = e + 1.0f;
    float y = __int_as_float(0x7EF311C3 - __float_as_int(d));
    y = y * (2.0f - d * y);
    y = y * (2.0f - d * y);
    return 1.0f - 2.0f * y;
}

// stage one k64 B chunk (rows x 128B) into a swizzled buffer; own group.
__device__ __forceinline__ void stageB_rows(uint32_t dst, const __nv_bfloat16* Bg0,
                                            int kc, int rows, int tid) {
    const __nv_bfloat16* Bg = Bg0 + kc * 64;
    const int n = rows >> 6;
    for (int i = 0; i < n; i++) {
        int idx = tid + (i << 9);
        int row = idx >> 3, c = idx & 7;
        cpa16(dst + row * 128 + ((c ^ (row & 7)) << 4),
              Bg + (size_t)row * D + c * 8);
    }
    asm volatile("cp.async.commit_group;" ::: "memory");
}

// --------------------------- prologue kernel --------------------------------
__global__ void prep_kernel(const float* __restrict__ W1,
                            const float* __restrict__ W2) {
    int idx = blockIdx.x * blockDim.x + threadIdx.x;
    int r = idx >> 8, c = idx & 255;
    __nv_bfloat16 v1 = __float2bfloat16(W1[idx]);
    __nv_bfloat16 v2 = __float2bfloat16(W2[idx]);
    g_W1b[idx] = v1;
    g_W2b[idx] = v2;
    g_W1Tb[c * D + r] = v1;
    g_W2Tb[c * D + r] = v2;
}

// ------------------------------ fused pass ----------------------------------
//  MODE 0: A = staged g_Sb, B = g_W1Tb -> H = tanh(acc + b1)
//  MODE 1: A = H tile,      B = g_W2Tb -> G = wout*(1 - tanh(acc+b2)^2)
//  MODE 2: A = G tile,      B = g_W2b  -> G = acc*(1 - H^2)   (in place)
//  MODE 3: A = G tile,      B = g_W1b  -> full kick (NT=2, N=256)
//  MODE 4: A = G tile,      B = g_W1b  -> half kick (NT=1, N=128)
// Warp tile: all F*16 CTA rows x (NT*8) cols; wn = wid * NT*8.
template <int MODE, int NT, int F>
__device__ __forceinline__ void pass_gemm(char* smem, uint32_t sbase,
                                          int m0, int cbm, int bs,
                                          const __nv_bfloat16* nextB, int nextRows,
                                          const float* __restrict__ b1g,
                                          const float* __restrict__ b2g,
                                          const float* __restrict__ wog) {
    const int tid  = threadIdx.x;
    const int wid  = tid >> 5;
    const int lane = tid & 31;
    const int g    = lane >> 2;
    const int t    = lane & 3;
    const int wn   = wid * (NT * 8);

    const uint32_t* Ht  = (const uint32_t*)(smem + OFF_H);
    uint32_t*       Htw = (uint32_t*)(smem + OFF_H);
    uint32_t*       Gt  = (uint32_t*)(smem + OFF_G);

    const __nv_bfloat16* Bsrc =
        (MODE == 0) ? g_W1Tb : (MODE == 1) ? g_W2Tb :
        (MODE == 2) ? g_W2b : g_W1b;

    const uint32_t Bbase = sbase + OFF_B0;
    const uint32_t Abase = sbase + OFF_A0;
    auto rotB = [&](uint32_t v) { return (v == Bbase + 2 * BBUF_SZ) ? Bbase : v + BBUF_SZ; };
    auto rotA = [&](uint32_t v) { return (v == Abase + 2 * ABUF_SZ) ? Abase : v + ABUF_SZ; };

    uint32_t curB = Bbase + (uint32_t)bs * BBUF_SZ;
    uint32_t curA = Abase + (uint32_t)bs * ABUF_SZ;
    uint32_t stgB = rotB(rotB(curB));
    uint32_t stgA = rotA(rotA(curA));

    auto stage = [&](int kc, uint32_t bdst, uint32_t adst) {
        const __nv_bfloat16* Bg = Bsrc + kc * 64;
#pragma unroll
        for (int i = 0; i < NT * 2; i++) {            // NT*128 rows x 8 chunks
            int idx = tid + (i << 9);
            int row = idx >> 3, c = idx & 7;
            cpa16(bdst + row * 128 + ((c ^ (row & 7)) << 4),
                  Bg + (size_t)row * D + c * 8);
        }
        if (MODE == 0) {
            const __nv_bfloat16* Ag = g_Sb + (size_t)m0 * D + kc * 64;
#pragma unroll
            for (int i = 0; i < 2; i++) {
                int idx = tid + (i << 9);
                int row = idx >> 3, c = idx & 7;
                if (row < cbm)
                    cpa16(adst + row * 128 + ((c ^ (row & 7)) << 4),
                          Ag + (size_t)row * D + c * 8);
            }
        }
        asm volatile("cp.async.commit_group;" ::: "memory");
    };
    auto stageA1 = [&](int kc, uint32_t adst) {
        const __nv_bfloat16* Ag = g_Sb + (size_t)m0 * D + kc * 64;
#pragma unroll
        for (int i = 0; i < 2; i++) {
            int idx = tid + (i << 9);
            int row = idx >> 3, c = idx & 7;
            if (row < cbm)
                cpa16(adst + row * 128 + ((c ^ (row & 7)) << 4),
                      Ag + (size_t)row * D + c * 8);
        }
        asm volatile("cp.async.commit_group;" ::: "memory");
    };

    if (MODE == 0) {
        __syncthreads();                 // g_Sb writes -> cp.async; frees G
        stageA1(0, curA);
        stageA1(1, rotA(curA));
    }

    float acc[F][NT][4];
#pragma unroll
    for (int f = 0; f < F; f++)
#pragma unroll
        for (int nf = 0; nf < NT; nf++)
#pragma unroll
            for (int r = 0; r < 4; r++) acc[f][nf][r] = 0.0f;

    // per-lane fragment address pieces
    const int      x7    = lane & 7;
    const int      akh   = lane >> 4;
    const uint32_t aRowS = (uint32_t)(lane & 15) * 128;             // staged A
    const uint32_t bRow  =
        (uint32_t)(wn + ((NT == 2) ? (((lane >> 4) << 3) + x7) : x7)) * 128;
    const int      bkh   = (lane >> 3) & 1;
    const int hi4w = akh << 2;
    const int row7 = x7 << 2;
    uint32_t rrb[F];
#pragma unroll
    for (int f = 0; f < F; f++)
        rrb[f] = sbase + ((MODE == 1) ? OFF_H : OFF_G) +
                 (uint32_t)(f * 16 + (lane & 15)) * 512;

#pragma unroll 1
    for (int kc = 0; kc < 4; kc++) {
        if (kc < 3) asm volatile("cp.async.wait_group 1;" ::: "memory");
        else        asm volatile("cp.async.wait_group 0;" ::: "memory");
        __syncthreads();
        if (kc < 2) stage(kc + 2, stgB, stgA);

        const uint32_t aB = curA + aRowS;
        const uint32_t bB = curB + bRow;

#pragma unroll
        for (int kk = 0; kk < 4; kk++) {
            const int kg = kc * 4 + kk;
            uint32_t a[F][4], bb[NT][2];
            if (MODE == 0) {
                const uint32_t sa = (uint32_t)((((kk << 1) + akh) ^ x7) << 4);
#pragma unroll
                for (int f = 0; f < F; f++) LDMX4(a[f], aB + f * 2048 + sa);
            } else {
                const uint32_t s4 = (uint32_t)((((kg << 3) + hi4w) ^ row7) << 2);
#pragma unroll
                for (int f = 0; f < F; f++) LDMX4(a[f], rrb[f] + s4);
            }
            if (NT == 2) {
                uint32_t r_[4];
                const uint32_t sb4 = (uint32_t)((((kk << 1) + bkh) ^ x7) << 4);
                LDMX4(r_, bB + sb4);
                bb[0][0] = r_[0];  bb[0][1] = r_[1];
                bb[NT-1][0] = r_[2];  bb[NT-1][1] = r_[3];
            } else {
                const uint32_t sb2 = (uint32_t)((((kk << 1) + bkh) ^ x7) << 4);
                LDMX2(bb[0], bB + sb2);
            }
#pragma unroll
            for (int f = 0; f < F; f++)
#pragma unroll
                for (int nf = 0; nf < NT; nf++)
                    mma16(acc[f][nf], a[f], bb[nf]);
        }
        curB = rotB(curB);  curA = rotA(curA);
        stgB = rotB(stgB);  stgA = rotA(stgA);
    }

    // cross-pass prefetch (bufs bs+1, bs+2 of next pass) — clobber-free
    if (nextB) {
        stageB_rows(curB, nextB, 0, nextRows, tid);
        stageB_rows(rotB(curB), nextB, 1, nextRows, tid);
    }
    if (MODE == 2) __syncthreads();   // in-place G overwrite: all reads done

    // ------------------------------ epilogue --------------------------------
#pragma unroll
    for (int f = 0; f < F; f++) {
        const int r = f * 16 + g;                // local row; r&7 == g
#pragma unroll
        for (int nf = 0; nf < NT; nf++) {
            const int nc = wn + nf * 8 + 2 * t;
            const int ws = (nc >> 1) ^ (g << 2);
            float c0 = acc[f][nf][0], c1 = acc[f][nf][1];
            float c2 = acc[f][nf][2], c3 = acc[f][nf][3];

            if (MODE == 0) {
                float bv0 = __ldg(b1g + nc), bv1 = __ldg(b1g + nc + 1);
                Htw[r * 128 + ws]       = pk2(ftanh(c0 + bv0), ftanh(c1 + bv1));
                Htw[(r + 8) * 128 + ws] = pk2(ftanh(c2 + bv0), ftanh(c3 + bv1));
            } else if (MODE == 1) {
                float bv0 = __ldg(b2g + nc), bv1 = __ldg(b2g + nc + 1);
                float wv0 = __ldg(wog + nc), wv1 = __ldg(wog + nc + 1);
                float t0 = ftanh(c0 + bv0), t1 = ftanh(c1 + bv1);
                float t2 = ftanh(c2 + bv0), t3 = ftanh(c3 + bv1);
                Gt[r * 128 + ws]       = pk2(wv0 * (1.0f - t0 * t0),
                                             wv1 * (1.0f - t1 * t1));
                Gt[(r + 8) * 128 + ws] = pk2(wv0 * (1.0f - t2 * t2),
                                             wv1 * (1.0f - t3 * t3));
            } else if (MODE == 2) {
                float2 h0 = up2(Ht[r * 128 + ws]);
                float2 h1 = up2(Ht[(r + 8) * 128 + ws]);
                Gt[r * 128 + ws]       = pk2(c0 * (1.0f - h0.x * h0.x),
                                             c1 * (1.0f - h0.y * h0.y));
                Gt[(r + 8) * 128 + ws] = pk2(c2 * (1.0f - h1.x * h1.x),
                                             c3 * (1.0f - h1.y * h1.y));
            } else {
                const int grow = m0 + r;
                const float dA = (grow < BHALF) ? DT_MAG : -DT_MAG;
                const float dB = (grow + 8 < BHALF) ? DT_MAG : -DT_MAG;
                if (NT == 1 || nc < FD) {        // p -= 0.5*dt*dH[:, :FD]
                    float2* S0 = (float2*)(g_S + (size_t)grow * D + FD + nc);
                    float2* S1 = (float2*)(g_S + (size_t)(grow + 8) * D + FD + nc);
                    float2 p0 = *S0, p1 = *S1;
                    p0.x -= 0.5f * dA * c0;  p0.y -= 0.5f * dA * c1;
                    p1.x -= 0.5f * dB * c2;  p1.y -= 0.5f * dB * c3;
                    *S0 = p0;  *S1 = p1;
                    *(uint32_t*)(g_Sb + (size_t)grow * D + FD + nc)       = pk2(p0.x, p0.y);
                    *(uint32_t*)(g_Sb + (size_t)(grow + 8) * D + FD + nc) = pk2(p1.x, p1.y);
                } else {                          // q += dt*dH[:, FD:]
                    const int qc = nc - FD;
                    float2* S0 = (float2*)(g_S + (size_t)grow * D + qc);
                    float2* S1 = (float2*)(g_S + (size_t)(grow + 8) * D + qc);
                    float2 q0 = *S0, q1 = *S1;
                    q0.x += dA * c0;  q0.y += dA * c1;
                    q1.x += dB * c2;  q1.y += dB * c3;
                    *S0 = q0;  *S1 = q1;
                    *(uint32_t*)(g_Sb + (size_t)grow * D + qc)       = pk2(q0.x, q0.y);
                    *(uint32_t*)(g_Sb + (size_t)(grow + 8) * D + qc) = pk2(q1.x, q1.y);
                }
            }
        }
    }
}

// run the 8 leapfrog iterations with compile-time F
template <int F>
__device__ __forceinline__ void run_evals(char* smem, uint32_t sbase,
                                          int m0, int cbm,
                                          const float* b1, const float* b2,
                                          const float* wo) {
    int bs = 0;
    auto inc = [&]() { bs = (bs == 2) ? 0 : bs + 1; };
#pragma unroll 1
    for (int it = 0; it < 8; it++) {
        pass_gemm<0, 2, F>(smem, sbase, m0, cbm, bs, g_W2Tb, 256, b1, b2, wo); inc();
        pass_gemm<1, 2, F>(smem, sbase, m0, cbm, bs, g_W2b, 256, b1, b2, wo);  inc();
        if ((it & 1) == 0) {
            pass_gemm<2, 2, F>(smem, sbase, m0, cbm, bs, g_W1b, 256, b1, b2, wo); inc();
            pass_gemm<3, 2, F>(smem, sbase, m0, cbm, bs, g_W1Tb, 256, b1, b2, wo); inc();
        } else {
            pass_gemm<2, 2, F>(smem, sbase, m0, cbm, bs, g_W1b, 128, b1, b2, wo); inc();
            if (it < 7) { pass_gemm<4, 1, F>(smem, sbase, m0, cbm, bs, g_W1Tb, 256, b1, b2, wo); }
            else        { pass_gemm<4, 1, F>(smem, sbase, m0, cbm, bs, nullptr, 0, b1, b2, wo); }
            inc();
        }
    }
}

// ------------------------------ fused kernel --------------------------------
__global__ void __launch_bounds__(NTH, 1)
fused_kernel(const float* __restrict__ b1, const float* __restrict__ b2,
             const float* __restrict__ wo, const float* __restrict__ x,
             float* __restrict__ out) {
    extern __shared__ __align__(1024) char smem[];
    const uint32_t sbase = smem_u32(smem);
    const int tid = threadIdx.x;
    const int cta = blockIdx.x;

    const int m0  = (cta < 146) ? cta * 112 : 16352;
    const int cbm = (cta < 146) ? 112 : 32;

    // prefetch first pass's B chunks (bufs 0,1) — overlaps init below
    stageB_rows(sbase + OFF_B0, g_W1Tb, 0, 256, tid);
    stageB_rows(sbase + OFF_B0 + BBUF_SZ, g_W1Tb, 1, 256, tid);

    // init this CTA's state rows from x (row-private)
    for (int i = tid; i < cbm * 128; i += NTH) {
        int r = i >> 7, f = i & 127;
        int grow = m0 + r;
        int xi = (grow < BHALF) ? grow : grow - BHALF;
        size_t xb = (size_t)xi * 8192;
        float xm  = x[xb + 4096 + f];
        float xm1 = x[xb + 3968 + f];
        float q = xm, p = xm - xm1;
        size_t srow = (size_t)grow * D;
        g_S[srow + f]      = q;
        g_S[srow + FD + f] = p;
        g_Sb[srow + f]      = __float2bfloat16(q);
        g_Sb[srow + FD + f] = __float2bfloat16(p);
    }

    if (cbm == 112) run_evals<7>(smem, sbase, m0, cbm, b1, b2, wo);
    else            run_evals<2>(smem, sbase, m0, cbm, b1, b2, wo);

    // output: this CTA's rows -> disjoint column ranges of out
    __syncthreads();   // kick-epilogue g_S writes visible to all threads
    for (int i = tid; i < cbm * 64; i += NTH) {
        int r = i >> 6, c4 = i & 63;
        int grow = m0 + r;
        float4 v = *(const float4*)(g_S + (size_t)grow * D + c4 * 4);
        int bwd = grow >= BHALF;
        float* orow = out + (size_t)(bwd ? grow - BHALF : grow) * 768;
        if (bwd) *(float4*)(orow + c4 * 4) = v;          // [q_b | p_b]
        else     *(float4*)(orow + 512 + c4 * 4) = v;    // [q_f | p_f]
    }
    for (int i = tid; i < cbm * 128; i += NTH) {
        int r = i >> 7, f = i & 127;
        int grow = m0 + r;
        if (grow < BHALF) {                              // fwd rows write mid
            size_t xb = (size_t)grow * 8192;
            float xm  = x[xb + 4096 + f];
            float xm1 = x[xb + 3968 + f];
            float* orow = out + (size_t)grow * 768;
            orow[256 + f] = xm;          // q_mid
            orow[384 + f] = xm - xm1;    // p_mid
        }
    }
}

// ---------------------------------------------------------------------------
extern "C" void kernel_launch(void* const* d_in, const int* in_sizes, int n_in,
                              void* d_out, int out_size) {
    const float* x    = (const float*)d_in[0];
    const float* W1   = (const float*)d_in[1];
    const float* b1   = (const float*)d_in[2];
    const float* W2   = (const float*)d_in[3];
    const float* b2   = (const float*)d_in[4];
    const float* Wout = (const float*)d_in[5];
    float* out = (float*)d_out;

    cudaFuncSetAttribute(fused_kernel,
                         cudaFuncAttributeMaxDynamicSharedMemorySize, SMEM_TOTAL);

    prep_kernel<<<D * D / 256, 256>>>(W1, W2);
    fused_kernel<<<147, NTH, SMEM_TOTAL>>>(b1, b2, Wout, x, out);
}

// round 15
// speedup vs baseline: 1.5405x; 1.0511x over previous
#include <cuda_runtime.h>
#include <cuda_bf16.h>
#include <math.h>
#include <cstdint>

// ============================================================================
// BiDirectionalSymplecticLayer — fused persistent kernel, 3-window edition.
// 146 CTAs x 112 rows + 1 CTA x 32 rows (grid 147); 16 n-split warps, warp
// tile = all CTA rows x 16 cols (F x 2 MMA/k-step, uniform). Per pass only
// THREE barrier windows: [chunks 0+1 | stage 2], [chunk 2 | stage 3],
// [chunk 3 | prefetch next pass]. MODE 2 writes its result into the H tile
// (per-thread in-place RAW) so its extra barrier is gone. bf16 m16n8k16.
// ============================================================================

#define D       256
#define FD      128
#define MTOT    16384
#define BHALF   8192
#define DT_MAG  0.1f
#define NTH     512

// smem layout (bytes) — tiles sized for up to 112 rows
#define OFF_H   0                        // T1 tile: H, then G1 (MODE2 output)
#define OFF_G   57344                    // T2 tile: G2; A bufs overlay here
#define OFF_A0  57344                    // A staging: 3 x (112 x 128B)
#define OFF_B0  114688                   // B staging: 3 x (256 x 128B)
#define ABUF_SZ 14336
#define BBUF_SZ 32768
#define SMEM_TOTAL (114688 + 3 * BBUF_SZ)   // 212992

__device__ float         g_S [MTOT * D];
__device__ __nv_bfloat16 g_Sb[MTOT * D];
__device__ __nv_bfloat16 g_W1b [D * D];    // W1  [n][k]
__device__ __nv_bfloat16 g_W2b [D * D];    // W2  [n][k]
__device__ __nv_bfloat16 g_W1Tb[D * D];    // W1^T [n][k]
__device__ __nv_bfloat16 g_W2Tb[D * D];    // W2^T [n][k]

// ------------------------------- helpers ------------------------------------
__device__ __forceinline__ void cpa16(uint32_t dst, const void* src) {
    asm volatile("cp.async.cg.shared.global [%0], [%1], 16;"
                 :: "r"(dst), "l"(src) : "memory");
}
__device__ __forceinline__ uint32_t smem_u32(const void* p) {
    uint32_t r;
    asm("{ .reg .u64 t; cvta.to.shared.u64 t, %1; cvt.u32.u64 %0, t; }"
        : "=r"(r) : "l"(p));
    return r;
}
__device__ __forceinline__ void mma16(float* c, const uint32_t* a, const uint32_t* b) {
    asm volatile(
        "mma.sync.aligned.m16n8k16.row.col.f32.bf16.bf16.f32 "
        "{%0,%1,%2,%3}, {%4,%5,%6,%7}, {%8,%9}, {%0,%1,%2,%3};"
        : "+f"(c[0]), "+f"(c[1]), "+f"(c[2]), "+f"(c[3])
        : "r"(a[0]), "r"(a[1]), "r"(a[2]), "r"(a[3]), "r"(b[0]), "r"(b[1]));
}
#define LDMX4(r, addr) \
    asm volatile("ldmatrix.sync.aligned.m8n8.x4.shared.b16 {%0,%1,%2,%3}, [%4];" \
                 : "=r"((r)[0]), "=r"((r)[1]), "=r"((r)[2]), "=r"((r)[3]) \
                 : "r"(addr))
#define LDMX2(r, addr) \
    asm volatile("ldmatrix.sync.aligned.m8n8.x2.shared.b16 {%0,%1}, [%2];" \
                 : "=r"((r)[0]), "=r"((r)[1]) \
                 : "r"(addr))
__device__ __forceinline__ uint32_t pk2(float x, float y) {
    __nv_bfloat162 h = __floats2bfloat162_rn(x, y);
    return *reinterpret_cast<uint32_t*>(&h);
}
__device__ __forceinline__ float2 up2(uint32_t u) {
    __nv_bfloat162 h = *reinterpret_cast<__nv_bfloat162*>(&u);
    return make_float2(__bfloat162float(h.x), __bfloat162float(h.y));
}
__device__ __forceinline__ float ftanh(float x) {
    x = fminf(20.0f, fmaxf(-20.0f, x));
    float e;
    asm("ex2.approx.f32 %0, %1;" : "=f"(e) : "f"(x * 2.885390082f));
    float d = e + 1.0f;
    float y = __int_as_float(0x7EF311C3 - __float_as_int(d));
    y = y * (2.0f - d * y);
    y = y * (2.0f - d * y);
    return 1.0f - 2.0f * y;
}

// stage one k64 B chunk (rows x 128B) into a swizzled buffer; own group.
__device__ __forceinline__ void stageB_rows(uint32_t dst, const __nv_bfloat16* Bg0,
                                            int kc, int rows, int tid) {
    const __nv_bfloat16* Bg = Bg0 + kc * 64;
    const int n = rows >> 6;
    for (int i = 0; i < n; i++) {
        int idx = tid + (i << 9);
        int row = idx >> 3, c = idx & 7;
        cpa16(dst + row * 128 + ((c ^ (row & 7)) << 4),
              Bg + (size_t)row * D + c * 8);
    }
    asm volatile("cp.async.commit_group;" ::: "memory");
}

// --------------------------- prologue kernel --------------------------------
__global__ void prep_kernel(const float* __restrict__ W1,
                            const float* __restrict__ W2) {
    int idx = blockIdx.x * blockDim.x + threadIdx.x;
    int r = idx >> 8, c = idx & 255;
    __nv_bfloat16 v1 = __float2bfloat16(W1[idx]);
    __nv_bfloat16 v2 = __float2bfloat16(W2[idx]);
    g_W1b[idx] = v1;
    g_W2b[idx] = v2;
    g_W1Tb[c * D + r] = v1;
    g_W2Tb[c * D + r] = v2;
}

// ------------------------------ fused pass ----------------------------------
//  MODE 0: A = staged g_Sb, B = g_W1Tb -> T1 = tanh(acc + b1)          [H]
//  MODE 1: A = T1,          B = g_W2Tb -> T2 = wout*(1-tanh(acc+b2)^2) [G2]
//  MODE 2: A = T2,          B = g_W2b  -> T1 = acc*(1 - T1^2)  (in-place RAW)
//  MODE 3: A = T1,          B = g_W1b  -> full kick (NT=2, N=256)
//  MODE 4: A = T1,          B = g_W1b  -> half kick (NT=1, N=128)
template <int MODE, int NT, int F>
__device__ __forceinline__ void pass_gemm(char* smem, uint32_t sbase,
                                          int m0, int cbm, int bs,
                                          const __nv_bfloat16* nextB, int nextRows,
                                          const float* __restrict__ b1g,
                                          const float* __restrict__ b2g,
                                          const float* __restrict__ wog) {
    const int tid  = threadIdx.x;
    const int wid  = tid >> 5;
    const int lane = tid & 31;
    const int g    = lane >> 2;
    const int t    = lane & 3;
    const int wn   = wid * (NT * 8);

    const uint32_t* Ht  = (const uint32_t*)(smem + OFF_H);
    uint32_t*       Htw = (uint32_t*)(smem + OFF_H);
    uint32_t*       Gt  = (uint32_t*)(smem + OFF_G);

    const __nv_bfloat16* Bsrc =
        (MODE == 0) ? g_W1Tb : (MODE == 1) ? g_W2Tb :
        (MODE == 2) ? g_W2b : g_W1b;

    uint32_t BB[3], AA[3];
#pragma unroll
    for (int i = 0; i < 3; i++) {
        int b = bs + i;  if (b >= 3) b -= 3;
        BB[i] = sbase + OFF_B0 + (uint32_t)b * BBUF_SZ;
        AA[i] = sbase + OFF_A0 + (uint32_t)b * ABUF_SZ;
    }

    auto stage = [&](int kc, uint32_t bdst, uint32_t adst) {
        const __nv_bfloat16* Bg = Bsrc + kc * 64;
#pragma unroll
        for (int i = 0; i < NT * 2; i++) {            // NT*128 rows x 8 chunks
            int idx = tid + (i << 9);
            int row = idx >> 3, c = idx & 7;
            cpa16(bdst + row * 128 + ((c ^ (row & 7)) << 4),
                  Bg + (size_t)row * D + c * 8);
        }
        if (MODE == 0) {
            const __nv_bfloat16* Ag = g_Sb + (size_t)m0 * D + kc * 64;
#pragma unroll
            for (int i = 0; i < 2; i++) {
                int idx = tid + (i << 9);
                int row = idx >> 3, c = idx & 7;
                if (row < cbm)
                    cpa16(adst + row * 128 + ((c ^ (row & 7)) << 4),
                          Ag + (size_t)row * D + c * 8);
            }
        }
        asm volatile("cp.async.commit_group;" ::: "memory");
    };
    auto stageA1 = [&](int kc, uint32_t adst) {
        const __nv_bfloat16* Ag = g_Sb + (size_t)m0 * D + kc * 64;
#pragma unroll
        for (int i = 0; i < 2; i++) {
            int idx = tid + (i << 9);
            int row = idx >> 3, c = idx & 7;
            if (row < cbm)
                cpa16(adst + row * 128 + ((c ^ (row & 7)) << 4),
                      Ag + (size_t)row * D + c * 8);
        }
        asm volatile("cp.async.commit_group;" ::: "memory");
    };

    if (MODE == 0) {
        // entry barrier: prior kick/init writes to g_Sb visible to cp.async;
        // also releases the T2/A-overlay region.
        __syncthreads();
        stageA1(0, AA[0]);
        stageA1(1, AA[1]);
    }

    float acc[F][NT][4];
#pragma unroll
    for (int f = 0; f < F; f++)
#pragma unroll
        for (int nf = 0; nf < NT; nf++)
#pragma unroll
            for (int r = 0; r < 4; r++) acc[f][nf][r] = 0.0f;

    // per-lane fragment address pieces
    const int      x7    = lane & 7;
    const int      akh   = lane >> 4;
    const uint32_t aRowS = (uint32_t)(lane & 15) * 128;             // staged A
    const uint32_t bRow  =
        (uint32_t)(wn + ((NT == 2) ? (((lane >> 4) << 3) + x7) : x7)) * 128;
    const int      bkh   = (lane >> 3) & 1;
    const int hi4w = akh << 2;
    const int row7 = x7 << 2;
    uint32_t rrb[F];
#pragma unroll
    for (int f = 0; f < F; f++)
        rrb[f] = sbase + ((MODE == 2) ? OFF_G : OFF_H) +
                 (uint32_t)(f * 16 + (lane & 15)) * 512;

    auto compute_chunk = [&](int kc, uint32_t bufB, uint32_t bufA) {
        const uint32_t aB = bufA + aRowS;
        const uint32_t bB = bufB + bRow;
#pragma unroll
        for (int kk = 0; kk < 4; kk++) {
            const int kg = kc * 4 + kk;
            uint32_t a[F][4], bb[NT][2];
            if (MODE == 0) {
                const uint32_t sa = (uint32_t)((((kk << 1) + akh) ^ x7) << 4);
#pragma unroll
                for (int f = 0; f < F; f++) LDMX4(a[f], aB + f * 2048 + sa);
            } else {
                const uint32_t s4 = (uint32_t)((((kg << 3) + hi4w) ^ row7) << 2);
#pragma unroll
                for (int f = 0; f < F; f++) LDMX4(a[f], rrb[f] + s4);
            }
            if (NT == 2) {
                uint32_t r_[4];
                const uint32_t sb4 = (uint32_t)((((kk << 1) + bkh) ^ x7) << 4);
                LDMX4(r_, bB + sb4);
                bb[0][0] = r_[0];  bb[0][1] = r_[1];
                bb[NT-1][0] = r_[2];  bb[NT-1][1] = r_[3];
            } else {
                const uint32_t sb2 = (uint32_t)((((kk << 1) + bkh) ^ x7) << 4);
                LDMX2(bb[0], bB + sb2);
            }
#pragma unroll
            for (int f = 0; f < F; f++)
#pragma unroll
                for (int nf = 0; nf < NT; nf++)
                    mma16(acc[f][nf], a[f], bb[nf]);
        }
    };

    // window A: chunks 0+1 (both prefetched); stage chunk 2
    asm volatile("cp.async.wait_group 0;" ::: "memory");
    __syncthreads();
    stage(2, BB[2], AA[2]);
    compute_chunk(0, BB[0], AA[0]);
    compute_chunk(1, BB[1], AA[1]);

    // window B: chunk 2; stage chunk 3 into buffer 0 (consumed in window A)
    asm volatile("cp.async.wait_group 0;" ::: "memory");
    __syncthreads();
    stage(3, BB[0], AA[0]);
    compute_chunk(2, BB[2], AA[2]);

    // window C: prefetch next pass's chunks 0,1 into buffers 1,2 (consumed in
    // windows A/B); compute chunk 3
    asm volatile("cp.async.wait_group 0;" ::: "memory");
    __syncthreads();
    if (nextB) {
        stageB_rows(BB[1], nextB, 0, nextRows, tid);
        stageB_rows(BB[2], nextB, 1, nextRows, tid);
    }
    compute_chunk(3, BB[0], AA[0]);

    // ------------------------------ epilogue --------------------------------
    // MODE 2 writes T1 in place of its own reads (same element per thread) —
    // no barrier required.
#pragma unroll
    for (int f = 0; f < F; f++) {
        const int r = f * 16 + g;                // local row; r&7 == g
#pragma unroll
        for (int nf = 0; nf < NT; nf++) {
            const int nc = wn + nf * 8 + 2 * t;
            const int ws = (nc >> 1) ^ (g << 2);
            float c0 = acc[f][nf][0], c1 = acc[f][nf][1];
            float c2 = acc[f][nf][2], c3 = acc[f][nf][3];

            if (MODE == 0) {
                float bv0 = __ldg(b1g + nc), bv1 = __ldg(b1g + nc + 1);
                Htw[r * 128 + ws]       = pk2(ftanh(c0 + bv0), ftanh(c1 + bv1));
                Htw[(r + 8) * 128 + ws] = pk2(ftanh(c2 + bv0), ftanh(c3 + bv1));
            } else if (MODE == 1) {
                float bv0 = __ldg(b2g + nc), bv1 = __ldg(b2g + nc + 1);
                float wv0 = __ldg(wog + nc), wv1 = __ldg(wog + nc + 1);
                float t0 = ftanh(c0 + bv0), t1 = ftanh(c1 + bv1);
                float t2 = ftanh(c2 + bv0), t3 = ftanh(c3 + bv1);
                Gt[r * 128 + ws]       = pk2(wv0 * (1.0f - t0 * t0),
                                             wv1 * (1.0f - t1 * t1));
                Gt[(r + 8) * 128 + ws] = pk2(wv0 * (1.0f - t2 * t2),
                                             wv1 * (1.0f - t3 * t3));
            } else if (MODE == 2) {
                float2 h0 = up2(Ht[r * 128 + ws]);
                float2 h1 = up2(Ht[(r + 8) * 128 + ws]);
                Htw[r * 128 + ws]       = pk2(c0 * (1.0f - h0.x * h0.x),
                                              c1 * (1.0f - h0.y * h0.y));
                Htw[(r + 8) * 128 + ws] = pk2(c2 * (1.0f - h1.x * h1.x),
                                              c3 * (1.0f - h1.y * h1.y));
            } else {
                const int grow = m0 + r;
                const float dA = (grow < BHALF) ? DT_MAG : -DT_MAG;
                const float dB = (grow + 8 < BHALF) ? DT_MAG : -DT_MAG;
                if (NT == 1 || nc < FD) {        // p -= 0.5*dt*dH[:, :FD]
                    float2* S0 = (float2*)(g_S + (size_t)grow * D + FD + nc);
                    float2* S1 = (float2*)(g_S + (size_t)(grow + 8) * D + FD + nc);
                    float2 p0 = *S0, p1 = *S1;
                    p0.x -= 0.5f * dA * c0;  p0.y -= 0.5f * dA * c1;
                    p1.x -= 0.5f * dB * c2;  p1.y -= 0.5f * dB * c3;
                    *S0 = p0;  *S1 = p1;
                    *(uint32_t*)(g_Sb + (size_t)grow * D + FD + nc)       = pk2(p0.x, p0.y);
                    *(uint32_t*)(g_Sb + (size_t)(grow + 8) * D + FD + nc) = pk2(p1.x, p1.y);
                } else {                          // q += dt*dH[:, FD:]
                    const int qc = nc - FD;
                    float2* S0 = (float2*)(g_S + (size_t)grow * D + qc);
                    float2* S1 = (float2*)(g_S + (size_t)(grow + 8) * D + qc);
                    float2 q0 = *S0, q1 = *S1;
                    q0.x += dA * c0;  q0.y += dA * c1;
                    q1.x += dB * c2;  q1.y += dB * c3;
                    *S0 = q0;  *S1 = q1;
                    *(uint32_t*)(g_Sb + (size_t)grow * D + qc)       = pk2(q0.x, q0.y);
                    *(uint32_t*)(g_Sb + (size_t)(grow + 8) * D + qc) = pk2(q1.x, q1.y);
                }
            }
        }
    }
    // no trailing barrier: the next pass's window-A wait+sync (or MODE 0's
    // entry barrier) orders all tile writes before any read.
}

// run the 8 leapfrog iterations with compile-time F
template <int F>
__device__ __forceinline__ void run_evals(char* smem, uint32_t sbase,
                                          int m0, int cbm,
                                          const float* b1, const float* b2,
                                          const float* wo) {
    int bs = 0;
    auto inc = [&]() { bs = (bs == 2) ? 0 : bs + 1; };
#pragma unroll 1
    for (int it = 0; it < 8; it++) {
        pass_gemm<0, 2, F>(smem, sbase, m0, cbm, bs, g_W2Tb, 256, b1, b2, wo); inc();
        pass_gemm<1, 2, F>(smem, sbase, m0, cbm, bs, g_W2b, 256, b1, b2, wo);  inc();
        if ((it & 1) == 0) {
            pass_gemm<2, 2, F>(smem, sbase, m0, cbm, bs, g_W1b, 256, b1, b2, wo); inc();
            pass_gemm<3, 2, F>(smem, sbase, m0, cbm, bs, g_W1Tb, 256, b1, b2, wo); inc();
        } else {
            pass_gemm<2, 2, F>(smem, sbase, m0, cbm, bs, g_W1b, 128, b1, b2, wo); inc();
            if (it < 7) { pass_gemm<4, 1, F>(smem, sbase, m0, cbm, bs, g_W1Tb, 256, b1, b2, wo); }
            else        { pass_gemm<4, 1, F>(smem, sbase, m0, cbm, bs, nullptr, 0, b1, b2, wo); }
            inc();
        }
    }
}

// ------------------------------ fused kernel --------------------------------
__global__ void __launch_bounds__(NTH, 1)
fused_kernel(const float* __restrict__ b1, const float* __restrict__ b2,
             const float* __restrict__ wo, const float* __restrict__ x,
             float* __restrict__ out) {
    extern __shared__ __align__(1024) char smem[];
    const uint32_t sbase = smem_u32(smem);
    const int tid = threadIdx.x;
    const int cta = blockIdx.x;

    const int m0  = (cta < 146) ? cta * 112 : 16352;
    const int cbm = (cta < 146) ? 112 : 32;

    // prefetch first pass's B chunks (bufs 0,1) — overlaps init below
    stageB_rows(sbase + OFF_B0, g_W1Tb, 0, 256, tid);
    stageB_rows(sbase + OFF_B0 + BBUF_SZ, g_W1Tb, 1, 256, tid);

    // init this CTA's state rows from x (row-private)
    for (int i = tid; i < cbm * 128; i += NTH) {
        int r = i >> 7, f = i & 127;
        int grow = m0 + r;
        int xi = (grow < BHALF) ? grow : grow - BHALF;
        size_t xb = (size_t)xi * 8192;
        float xm  = x[xb + 4096 + f];
        float xm1 = x[xb + 3968 + f];
        float q = xm, p = xm - xm1;
        size_t srow = (size_t)grow * D;
        g_S[srow + f]      = q;
        g_S[srow + FD + f] = p;
        g_Sb[srow + f]      = __float2bfloat16(q);
        g_Sb[srow + FD + f] = __float2bfloat16(p);
    }

    if (cbm == 112) run_evals<7>(smem, sbase, m0, cbm, b1, b2, wo);
    else            run_evals<2>(smem, sbase, m0, cbm, b1, b2, wo);

    // output: this CTA's rows -> disjoint column ranges of out
    __syncthreads();   // kick-epilogue g_S writes visible to all threads
    for (int i = tid; i < cbm * 64; i += NTH) {
        int r = i >> 6, c4 = i & 63;
        int grow = m0 + r;
        float4 v = *(const float4*)(g_S + (size_t)grow * D + c4 * 4);
        int bwd = grow >= BHALF;
        float* orow = out + (size_t)(bwd ? grow - BHALF : grow) * 768;
        if (bwd) *(float4*)(orow + c4 * 4) = v;          // [q_b | p_b]
        else     *(float4*)(orow + 512 + c4 * 4) = v;    // [q_f | p_f]
    }
    for (int i = tid; i < cbm * 128; i += NTH) {
        int r = i >> 7, f = i & 127;
        int grow = m0 + r;
        if (grow < BHALF) {                              // fwd rows write mid
            size_t xb = (size_t)grow * 8192;
            float xm  = x[xb + 4096 + f];
            float xm1 = x[xb + 3968 + f];
            float* orow = out + (size_t)grow * 768;
            orow[256 + f] = xm;          // q_mid
            orow[384 + f] = xm - xm1;    // p_mid
        }
    }
}

// ---------------------------------------------------------------------------
extern "C" void kernel_launch(void* const* d_in, const int* in_sizes, int n_in,
                              void* d_out, int out_size) {
    const float* x    = (const float*)d_in[0];
    const float* W1   = (const float*)d_in[1];
    const float* b1   = (const float*)d_in[2];
    const float* W2   = (const float*)d_in[3];
    const float* b2   = (const float*)d_in[4];
    const float* Wout = (const float*)d_in[5];
    float* out = (float*)d_out;

    cudaFuncSetAttribute(fused_kernel,
                         cudaFuncAttributeMaxDynamicSharedMemorySize, SMEM_TOTAL);

    prep_kernel<<<D * D / 256, 256>>>(W1, W2);
    fused_kernel<<<147, NTH, SMEM_TOTAL>>>(b1, b2, Wout, x, out);
}

// round 16
// speedup vs baseline: 1.6642x; 1.0803x over previous
#include <cuda_runtime.h>
#include <cuda_bf16.h>
#include <math.h>
#include <cstdint>

// ============================================================================
// BiDirectionalSymplecticLayer — fused persistent kernel, smem-state edition.
// 146 CTAs x 112 rows + 1 CTA x 32 rows (grid 147); 16 n-split warps, warp
// tile = all CTA rows x 16 cols. 3 barrier windows per pass. The bf16 state
// shadow lives IN SHARED MEMORY (T2-region overlay, staged-A chunk layout):
// kick epilogues write it directly, MODE 0 reads fragments from it — no
// global g_Sb, no A staging, no MODE-0 entry barrier. bf16 m16n8k16.
// ============================================================================

#define D       256
#define FD      128
#define MTOT    16384
#define BHALF   8192
#define DT_MAG  0.1f
#define NTH     512

// smem layout (bytes)
#define OFF_H   0                        // T1: H, then G1 (MODE2 in-place)
#define OFF_G   57344                    // T2: G2  /  bf16 state (A-chunk layout)
#define OFF_B0  114688                   // B staging: 3 x (256 x 128B)
#define BBUF_SZ 32768
#define ACH_SZ  14336                    // one k64 A-chunk: 112 x 128B
#define SMEM_TOTAL (114688 + 3 * BBUF_SZ)   // 212992

__device__ float         g_S [MTOT * D];   // fp32 master state [q|p]
__device__ __nv_bfloat16 g_W1b [D * D];    // W1  [n][k]
__device__ __nv_bfloat16 g_W2b [D * D];    // W2  [n][k]
__device__ __nv_bfloat16 g_W1Tb[D * D];    // W1^T [n][k]
__device__ __nv_bfloat16 g_W2Tb[D * D];    // W2^T [n][k]

// ------------------------------- helpers ------------------------------------
__device__ __forceinline__ void cpa16(uint32_t dst, const void* src) {
    asm volatile("cp.async.cg.shared.global [%0], [%1], 16;"
                 :: "r"(dst), "l"(src) : "memory");
}
__device__ __forceinline__ uint32_t smem_u32(const void* p) {
    uint32_t r;
    asm("{ .reg .u64 t; cvta.to.shared.u64 t, %1; cvt.u32.u64 %0, t; }"
        : "=r"(r) : "l"(p));
    return r;
}
__device__ __forceinline__ void mma16(float* c, const uint32_t* a, const uint32_t* b) {
    asm volatile(
        "mma.sync.aligned.m16n8k16.row.col.f32.bf16.bf16.f32 "
        "{%0,%1,%2,%3}, {%4,%5,%6,%7}, {%8,%9}, {%0,%1,%2,%3};"
        : "+f"(c[0]), "+f"(c[1]), "+f"(c[2]), "+f"(c[3])
        : "r"(a[0]), "r"(a[1]), "r"(a[2]), "r"(a[3]), "r"(b[0]), "r"(b[1]));
}
#define LDMX4(r, addr) \
    asm volatile("ldmatrix.sync.aligned.m8n8.x4.shared.b16 {%0,%1,%2,%3}, [%4];" \
                 : "=r"((r)[0]), "=r"((r)[1]), "=r"((r)[2]), "=r"((r)[3]) \
                 : "r"(addr))
#define LDMX2(r, addr) \
    asm volatile("ldmatrix.sync.aligned.m8n8.x2.shared.b16 {%0,%1}, [%2];" \
                 : "=r"((r)[0]), "=r"((r)[1]) \
                 : "r"(addr))
__device__ __forceinline__ uint32_t pk2(float x, float y) {
    __nv_bfloat162 h = __floats2bfloat162_rn(x, y);
    return *reinterpret_cast<uint32_t*>(&h);
}
__device__ __forceinline__ float2 up2(uint32_t u) {
    __nv_bfloat162 h = *reinterpret_cast<__nv_bfloat162*>(&u);
    return make_float2(__bfloat162float(h.x), __bfloat162float(h.y));
}
__device__ __forceinline__ float ftanh(float x) {
    x = fminf(20.0f, fmaxf(-20.0f, x));
    float e;
    asm("ex2.approx.f32 %0, %1;" : "=f"(e) : "f"(x * 2.885390082f));
    float d = e + 1.0f;
    float y = __int_as_float(0x7EF311C3 - __float_as_int(d));
    y = y * (2.0f - d * y);
    y = y * (2.0f - d * y);
    return 1.0f - 2.0f * y;
}
// byte offset (from smem base) of state element (local row r, state col sc)
// in the staged-A chunk layout: chunk = sc/64, rows of 128B, 16B-chunk swizzle.
__device__ __forceinline__ uint32_t st_addr(int r, int sc) {
    int ch = sc >> 6, cl = sc & 63;
    return (uint32_t)(OFF_G + ch * ACH_SZ + r * 128 +
                      ((((cl >> 3) ^ (r & 7)) << 4) | ((cl << 1) & 15)));
}

// stage one k64 B chunk (rows x 128B) into a swizzled buffer; own group.
__device__ __forceinline__ void stageB_rows(uint32_t dst, const __nv_bfloat16* Bg0,
                                            int kc, int rows, int tid) {
    const __nv_bfloat16* Bg = Bg0 + kc * 64;
    const int n = rows >> 6;
    for (int i = 0; i < n; i++) {
        int idx = tid + (i << 9);
        int row = idx >> 3, c = idx & 7;
        cpa16(dst + row * 128 + ((c ^ (row & 7)) << 4),
              Bg + (size_t)row * D + c * 8);
    }
    asm volatile("cp.async.commit_group;" ::: "memory");
}

// --------------------------- prologue kernel --------------------------------
__global__ void prep_kernel(const float* __restrict__ W1,
                            const float* __restrict__ W2) {
    int idx = blockIdx.x * blockDim.x + threadIdx.x;
    int r = idx >> 8, c = idx & 255;
    __nv_bfloat16 v1 = __float2bfloat16(W1[idx]);
    __nv_bfloat16 v2 = __float2bfloat16(W2[idx]);
    g_W1b[idx] = v1;
    g_W2b[idx] = v2;
    g_W1Tb[c * D + r] = v1;
    g_W2Tb[c * D + r] = v2;
}

// ------------------------------ fused pass ----------------------------------
//  MODE 0: A = smem state,  B = g_W1Tb -> T1 = tanh(acc + b1)          [H]
//  MODE 1: A = T1,          B = g_W2Tb -> T2 = wout*(1-tanh(acc+b2)^2) [G2]
//  MODE 2: A = T2,          B = g_W2b  -> T1 = acc*(1 - T1^2) (in-place RAW)
//  MODE 3: A = T1,          B = g_W1b  -> full kick; state -> smem (T2 region)
//  MODE 4: A = T1,          B = g_W1b  -> half kick (p) + q refresh from g_S
template <int MODE, int NT, int F>
__device__ __forceinline__ void pass_gemm(char* smem, uint32_t sbase,
                                          int m0, int cbm, int bs,
                                          const __nv_bfloat16* nextB, int nextRows,
                                          const float* __restrict__ b1g,
                                          const float* __restrict__ b2g,
                                          const float* __restrict__ wog) {
    const int tid  = threadIdx.x;
    const int wid  = tid >> 5;
    const int lane = tid & 31;
    const int g    = lane >> 2;
    const int t    = lane & 3;
    const int wn   = wid * (NT * 8);

    const uint32_t* Ht  = (const uint32_t*)(smem + OFF_H);
    uint32_t*       Htw = (uint32_t*)(smem + OFF_H);
    uint32_t*       Gt  = (uint32_t*)(smem + OFF_G);

    const __nv_bfloat16* Bsrc =
        (MODE == 0) ? g_W1Tb : (MODE == 1) ? g_W2Tb :
        (MODE == 2) ? g_W2b : g_W1b;

    uint32_t BB[3];
#pragma unroll
    for (int i = 0; i < 3; i++) {
        int b = bs + i;  if (b >= 3) b -= 3;
        BB[i] = sbase + OFF_B0 + (uint32_t)b * BBUF_SZ;
    }

    float acc[F][NT][4];
#pragma unroll
    for (int f = 0; f < F; f++)
#pragma unroll
        for (int nf = 0; nf < NT; nf++)
#pragma unroll
            for (int r = 0; r < 4; r++) acc[f][nf][r] = 0.0f;

    // per-lane fragment address pieces
    const int      x7    = lane & 7;
    const int      akh   = lane >> 4;
    const uint32_t aRowS = (uint32_t)(lane & 15) * 128;       // state-chunk A
    const uint32_t bRow  =
        (uint32_t)(wn + ((NT == 2) ? (((lane >> 4) << 3) + x7) : x7)) * 128;
    const int      bkh   = (lane >> 3) & 1;
    const int hi4w = akh << 2;
    const int row7 = x7 << 2;
    uint32_t rrb[F];
#pragma unroll
    for (int f = 0; f < F; f++)
        rrb[f] = sbase + ((MODE == 2) ? OFF_G : OFF_H) +
                 (uint32_t)(f * 16 + (lane & 15)) * 512;

    auto compute_chunk = [&](int kc, uint32_t bufB) {
        const uint32_t aB = sbase + OFF_G + (uint32_t)kc * ACH_SZ + aRowS;
        const uint32_t bB = bufB + bRow;
#pragma unroll
        for (int kk = 0; kk < 4; kk++) {
            const int kg = kc * 4 + kk;
            uint32_t a[F][4], bb[NT][2];
            if (MODE == 0) {
                const uint32_t sa = (uint32_t)((((kk << 1) + akh) ^ x7) << 4);
#pragma unroll
                for (int f = 0; f < F; f++) LDMX4(a[f], aB + f * 2048 + sa);
            } else {
                const uint32_t s4 = (uint32_t)((((kg << 3) + hi4w) ^ row7) << 2);
#pragma unroll
                for (int f = 0; f < F; f++) LDMX4(a[f], rrb[f] + s4);
            }
            if (NT == 2) {
                uint32_t r_[4];
                const uint32_t sb4 = (uint32_t)((((kk << 1) + bkh) ^ x7) << 4);
                LDMX4(r_, bB + sb4);
                bb[0][0] = r_[0];  bb[0][1] = r_[1];
                bb[NT-1][0] = r_[2];  bb[NT-1][1] = r_[3];
            } else {
                const uint32_t sb2 = (uint32_t)((((kk << 1) + bkh) ^ x7) << 4);
                LDMX2(bb[0], bB + sb2);
            }
#pragma unroll
            for (int f = 0; f < F; f++)
#pragma unroll
                for (int nf = 0; nf < NT; nf++)
                    mma16(acc[f][nf], a[f], bb[nf]);
        }
    };

    // window A: chunks 0+1 (both prefetched by previous pass); stage chunk 2.
    // The sync also orders the previous epilogue's smem writes (state / tiles).
    asm volatile("cp.async.wait_group 0;" ::: "memory");
    __syncthreads();
    stageB_rows(BB[2], Bsrc, 2, NT * 128, tid);
    compute_chunk(0, BB[0]);
    compute_chunk(1, BB[1]);

    // window B: chunk 2; stage chunk 3 into buffer 0 (consumed in window A)
    asm volatile("cp.async.wait_group 0;" ::: "memory");
    __syncthreads();
    stageB_rows(BB[0], Bsrc, 3, NT * 128, tid);
    compute_chunk(2, BB[2]);

    // window C: prefetch next pass's chunks 0,1 into buffers 1,2; compute 3
    asm volatile("cp.async.wait_group 0;" ::: "memory");
    __syncthreads();
    if (nextB) {
        stageB_rows(BB[1], nextB, 0, nextRows, tid);
        stageB_rows(BB[2], nextB, 1, nextRows, tid);
    }
    compute_chunk(3, BB[0]);

    // ------------------------------ epilogue --------------------------------
#pragma unroll
    for (int f = 0; f < F; f++) {
        const int r = f * 16 + g;                // local row; r&7 == g
#pragma unroll
        for (int nf = 0; nf < NT; nf++) {
            const int nc = wn + nf * 8 + 2 * t;
            const int ws = (nc >> 1) ^ (g << 2);
            float c0 = acc[f][nf][0], c1 = acc[f][nf][1];
            float c2 = acc[f][nf][2], c3 = acc[f][nf][3];

            if (MODE == 0) {
                float bv0 = __ldg(b1g + nc), bv1 = __ldg(b1g + nc + 1);
                Htw[r * 128 + ws]       = pk2(ftanh(c0 + bv0), ftanh(c1 + bv1));
                Htw[(r + 8) * 128 + ws] = pk2(ftanh(c2 + bv0), ftanh(c3 + bv1));
            } else if (MODE == 1) {
                float bv0 = __ldg(b2g + nc), bv1 = __ldg(b2g + nc + 1);
                float wv0 = __ldg(wog + nc), wv1 = __ldg(wog + nc + 1);
                float t0 = ftanh(c0 + bv0), t1 = ftanh(c1 + bv1);
                float t2 = ftanh(c2 + bv0), t3 = ftanh(c3 + bv1);
                Gt[r * 128 + ws]       = pk2(wv0 * (1.0f - t0 * t0),
                                             wv1 * (1.0f - t1 * t1));
                Gt[(r + 8) * 128 + ws] = pk2(wv0 * (1.0f - t2 * t2),
                                             wv1 * (1.0f - t3 * t3));
            } else if (MODE == 2) {
                float2 h0 = up2(Ht[r * 128 + ws]);
                float2 h1 = up2(Ht[(r + 8) * 128 + ws]);
                Htw[r * 128 + ws]       = pk2(c0 * (1.0f - h0.x * h0.x),
                                              c1 * (1.0f - h0.y * h0.y));
                Htw[(r + 8) * 128 + ws] = pk2(c2 * (1.0f - h1.x * h1.x),
                                              c3 * (1.0f - h1.y * h1.y));
            } else {
                const int grow = m0 + r;
                const float dA = (grow < BHALF) ? DT_MAG : -DT_MAG;
                const float dB = (grow + 8 < BHALF) ? DT_MAG : -DT_MAG;
                if (NT == 1 || nc < FD) {        // p -= 0.5*dt*dH[:, :FD]
                    const int sc = FD + nc;      // state column
                    float2* S0 = (float2*)(g_S + (size_t)grow * D + sc);
                    float2* S1 = (float2*)(g_S + (size_t)(grow + 8) * D + sc);
                    float2 p0 = *S0, p1 = *S1;
                    p0.x -= 0.5f * dA * c0;  p0.y -= 0.5f * dA * c1;
                    p1.x -= 0.5f * dB * c2;  p1.y -= 0.5f * dB * c3;
                    *S0 = p0;  *S1 = p1;
                    *(uint32_t*)(smem + st_addr(r, sc))     = pk2(p0.x, p0.y);
                    *(uint32_t*)(smem + st_addr(r + 8, sc)) = pk2(p1.x, p1.y);
                } else {                          // q += dt*dH[:, FD:]
                    const int sc = nc - FD;
                    float2* S0 = (float2*)(g_S + (size_t)grow * D + sc);
                    float2* S1 = (float2*)(g_S + (size_t)(grow + 8) * D + sc);
                    float2 q0 = *S0, q1 = *S1;
                    q0.x += dA * c0;  q0.y += dA * c1;
                    q1.x += dB * c2;  q1.y += dB * c3;
                    *S0 = q0;  *S1 = q1;
                    *(uint32_t*)(smem + st_addr(r, sc))     = pk2(q0.x, q0.y);
                    *(uint32_t*)(smem + st_addr(r + 8, sc)) = pk2(q1.x, q1.y);
                }
            }
        }
    }

    // MODE 4 only kicked p; rebuild the q chunks of the smem state from the
    // fp32 master (q last updated by MODE 3, many barriers ago). Skip on the
    // final pass (nextB == nullptr): no further MODE 0 consumes it.
    if (MODE == 4 && nextB) {
        for (int i = tid; i < cbm * 64; i += NTH) {
            int r = i >> 6, sc = (i & 63) * 2;
            float2 v = *(const float2*)(g_S + (size_t)(m0 + r) * D + sc);
            *(uint32_t*)(smem + st_addr(r, sc)) = pk2(v.x, v.y);
        }
    }
    // no trailing barrier: the next pass's window-A wait+sync orders all
    // epilogue smem writes before any read.
}

// run the 8 leapfrog iterations with compile-time F
template <int F>
__device__ __forceinline__ void run_evals(char* smem, uint32_t sbase,
                                          int m0, int cbm,
                                          const float* b1, const float* b2,
                                          const float* wo) {
    int bs = 0;
    auto inc = [&]() { bs = (bs == 2) ? 0 : bs + 1; };
#pragma unroll 1
    for (int it = 0; it < 8; it++) {
        pass_gemm<0, 2, F>(smem, sbase, m0, cbm, bs, g_W2Tb, 256, b1, b2, wo); inc();
        pass_gemm<1, 2, F>(smem, sbase, m0, cbm, bs, g_W2b, 256, b1, b2, wo);  inc();
        if ((it & 1) == 0) {
            pass_gemm<2, 2, F>(smem, sbase, m0, cbm, bs, g_W1b, 256, b1, b2, wo); inc();
            pass_gemm<3, 2, F>(smem, sbase, m0, cbm, bs, g_W1Tb, 256, b1, b2, wo); inc();
        } else {
            pass_gemm<2, 2, F>(smem, sbase, m0, cbm, bs, g_W1b, 128, b1, b2, wo); inc();
            if (it < 7) { pass_gemm<4, 1, F>(smem, sbase, m0, cbm, bs, g_W1Tb, 256, b1, b2, wo); }
            else        { pass_gemm<4, 1, F>(smem, sbase, m0, cbm, bs, nullptr, 0, b1, b2, wo); }
            inc();
        }
    }
}

// ------------------------------ fused kernel --------------------------------
__global__ void __launch_bounds__(NTH, 1)
fused_kernel(const float* __restrict__ b1, const float* __restrict__ b2,
             const float* __restrict__ wo, const float* __restrict__ x,
             float* __restrict__ out) {
    extern __shared__ __align__(1024) char smem[];
    const uint32_t sbase = smem_u32(smem);
    const int tid = threadIdx.x;
    const int cta = blockIdx.x;

    const int m0  = (cta < 146) ? cta * 112 : 16352;
    const int cbm = (cta < 146) ? 112 : 32;

    // prefetch first pass's B chunks (bufs 0,1) — overlaps init below
    stageB_rows(sbase + OFF_B0, g_W1Tb, 0, 256, tid);
    stageB_rows(sbase + OFF_B0 + BBUF_SZ, g_W1Tb, 1, 256, tid);

    // init this CTA's state: fp32 master in global, bf16 shadow in smem
    for (int i = tid; i < cbm * 128; i += NTH) {
        int r = i >> 7, f = i & 127;
        int grow = m0 + r;
        int xi = (grow < BHALF) ? grow : grow - BHALF;
        size_t xb = (size_t)xi * 8192;
        float xm  = x[xb + 4096 + f];
        float xm1 = x[xb + 3968 + f];
        float q = xm, p = xm - xm1;
        size_t srow = (size_t)grow * D;
        g_S[srow + f]      = q;
        g_S[srow + FD + f] = p;
        *(__nv_bfloat16*)(smem + st_addr(r, f))      = __float2bfloat16(q);
        *(__nv_bfloat16*)(smem + st_addr(r, FD + f)) = __float2bfloat16(p);
    }
    // (first pass's window-A barrier orders these smem writes)

    if (cbm == 112) run_evals<7>(smem, sbase, m0, cbm, b1, b2, wo);
    else            run_evals<2>(smem, sbase, m0, cbm, b1, b2, wo);

    // output: this CTA's rows -> disjoint column ranges of out
    __syncthreads();   // kick-epilogue g_S writes visible to all threads
    for (int i = tid; i < cbm * 64; i += NTH) {
        int r = i >> 6, c4 = i & 63;
        int grow = m0 + r;
        float4 v = *(const float4*)(g_S + (size_t)grow * D + c4 * 4);
        int bwd = grow >= BHALF;
        float* orow = out + (size_t)(bwd ? grow - BHALF : grow) * 768;
        if (bwd) *(float4*)(orow + c4 * 4) = v;          // [q_b | p_b]
        else     *(float4*)(orow + 512 + c4 * 4) = v;    // [q_f | p_f]
    }
    for (int i = tid; i < cbm * 128; i += NTH) {
        int r = i >> 7, f = i & 127;
        int grow = m0 + r;
        if (grow < BHALF) {                              // fwd rows write mid
            size_t xb = (size_t)grow * 8192;
            float xm  = x[xb + 4096 + f];
            float xm1 = x[xb + 3968 + f];
            float* orow = out + (size_t)grow * 768;
            orow[256 + f] = xm;          // q_mid
            orow[384 + f] = xm - xm1;    // p_mid
        }
    }
}

// ---------------------------------------------------------------------------
extern "C" void kernel_launch(void* const* d_in, const int* in_sizes, int n_in,
                              void* d_out, int out_size) {
    const float* x    = (const float*)d_in[0];
    const float* W1   = (const float*)d_in[1];
    const float* b1   = (const float*)d_in[2];
    const float* W2   = (const float*)d_in[3];
    const float* b2   = (const float*)d_in[4];
    const float* Wout = (const float*)d_in[5];
    float* out = (float*)d_out;

    cudaFuncSetAttribute(fused_kernel,
                         cudaFuncAttributeMaxDynamicSharedMemorySize, SMEM_TOTAL);

    prep_kernel<<<D * D / 256, 256>>>(W1, W2);
    fused_kernel<<<147, NTH, SMEM_TOTAL>>>(b1, b2, Wout, x, out);
}